// round 7
// baseline (speedup 1.0000x reference)
#include <cuda_runtime.h>
#include <cuda_bf16.h>
#include <stdint.h>

#define BB 16384
#define D_SUP 1024
#define D_ANOM 128
#define D_IND 2048
#define D_IN 3200
#define H1 256
#define FEAT 128
#define DEPTH 12
#define NCOND 14
#define CAP 256

// ---------------- scratch (device globals; no allocation allowed) ----------
__device__ int8_t g_Aqh[BB * D_IN];                  // A hi plane [16384][3200]
__device__ int8_t g_Aql[BB * D_IN];                  // A lo plane
__device__ int8_t g_Wqh[H1 * D_IN];                  // W1^T hi plane [256][3200]
__device__ int8_t g_Wql[H1 * D_IN];
__device__ float g_sA[BB];                           // rowmax/32256
__device__ float g_sW[H1];                           // colmax/32256
__device__ __nv_bfloat16 g_Wh2[FEAT * H1];           // W2^T hi [128][256]
__device__ __nv_bfloat16 g_Wl2[FEAT * H1];
__device__ __nv_bfloat16 g_WhC[DEPTH * FEAT * FEAT]; // consW^T hi [12][128][128]
__device__ __nv_bfloat16 g_WlC[DEPTH * FEAT * FEAT];
__device__ __nv_bfloat16 g_h1h[BB * H1];             // h1 hi/lo [16384][256]
__device__ __nv_bfloat16 g_h1l[BB * H1];
__device__ __nv_bfloat16 g_WfinH[NCOND * 256 * FEAT]; // [k][256][128]: rows 0-127 retW^T, 128-255 Mk^T
__device__ __nv_bfloat16 g_WfinL[NCOND * 256 * FEAT];
__device__ float g_aw[BB];

// ---------------- helpers --------------------------------------------------
__device__ __forceinline__ uint32_t smem_u32(const void* p) {
    uint32_t a;
    asm("{ .reg .u64 t; cvta.to.shared.u64 t, %1; cvt.u32.u64 %0, t; }" : "=r"(a) : "l"(p));
    return a;
}
__device__ __forceinline__ void ldsm4(uint32_t* r, uint32_t addr) {
    asm volatile("ldmatrix.sync.aligned.m8n8.x4.shared.b16 {%0,%1,%2,%3}, [%4];"
                 : "=r"(r[0]), "=r"(r[1]), "=r"(r[2]), "=r"(r[3]) : "r"(addr));
}
__device__ __forceinline__ void mma_bf16(float* c, const uint32_t* a, const uint32_t* b) {
    asm volatile("mma.sync.aligned.m16n8k16.row.col.f32.bf16.bf16.f32 "
                 "{%0,%1,%2,%3}, {%4,%5,%6,%7}, {%8,%9}, {%0,%1,%2,%3};"
                 : "+f"(c[0]), "+f"(c[1]), "+f"(c[2]), "+f"(c[3])
                 : "r"(a[0]), "r"(a[1]), "r"(a[2]), "r"(a[3]), "r"(b[0]), "r"(b[1]));
}
__device__ __forceinline__ void mma_s8(int32_t* c, const uint32_t* a, const uint32_t* b) {
    asm volatile("mma.sync.aligned.m16n8k32.row.col.s32.s8.s8.s32 "
                 "{%0,%1,%2,%3}, {%4,%5,%6,%7}, {%8,%9}, {%0,%1,%2,%3};"
                 : "+r"(c[0]), "+r"(c[1]), "+r"(c[2]), "+r"(c[3])
                 : "r"(a[0]), "r"(a[1]), "r"(a[2]), "r"(a[3]), "r"(b[0]), "r"(b[1]));
}
__device__ __forceinline__ void cp16(uint32_t smem, const void* g) {
    asm volatile("cp.async.cg.shared.global [%0], [%1], 16;" :: "r"(smem), "l"(g));
}
#define CP_COMMIT() asm volatile("cp.async.commit_group;" ::: "memory")
#define CP_WAIT0()  asm volatile("cp.async.wait_group 0;" ::: "memory")
#define CP_WAIT1()  asm volatile("cp.async.wait_group 1;" ::: "memory")

// fixed-point split of qx (|qx| <= 32256) into hi/lo int8
__device__ __forceinline__ void split16(float x, float f, int8_t& h, int8_t& l) {
    int qx = (int)rintf(x * f);
    int hi = (qx + 128) >> 8;
    h = (int8_t)hi;
    l = (int8_t)(qx - (hi << 8));
}

// ---------------- quantW: W1 [3200][256] -> int8 planes [256][3200] + scale
__global__ __launch_bounds__(128) void quantW_kernel(const float* __restrict__ W1,
                                                     int8_t* __restrict__ Wqh,
                                                     int8_t* __restrict__ Wql,
                                                     float* __restrict__ sW) {
    const int n = blockIdx.x;
    const int tid = threadIdx.x;
    __shared__ float red[4];
    __shared__ float fsh;
    float m = 0.f;
    for (int k = tid; k < D_IN; k += 128)
        m = fmaxf(m, fabsf(W1[(size_t)k * H1 + n]));
    #pragma unroll
    for (int o = 16; o; o >>= 1) m = fmaxf(m, __shfl_xor_sync(0xFFFFFFFFu, m, o));
    if ((tid & 31) == 0) red[tid >> 5] = m;
    __syncthreads();
    if (tid == 0) {
        float mm = fmaxf(fmaxf(red[0], red[1]), fmaxf(red[2], red[3]));
        mm = fmaxf(mm, 1e-30f);
        fsh = 32256.f / mm;
        sW[n] = mm / 32256.f;
    }
    __syncthreads();
    const float f = fsh;
    for (int k = tid; k < D_IN; k += 128) {
        int8_t h, l;
        split16(W1[(size_t)k * H1 + n], f, h, l);
        Wqh[(size_t)n * D_IN + k] = h;
        Wql[(size_t)n * D_IN + k] = l;
    }
}

// ---------------- quantA: concat(sup,anom,ind) row -> int8 planes + scale ---
__global__ __launch_bounds__(128) void quantA_kernel(const float* __restrict__ sup,
                                                     const float* __restrict__ anom,
                                                     const float* __restrict__ ind,
                                                     int8_t* __restrict__ Aqh,
                                                     int8_t* __restrict__ Aql,
                                                     float* __restrict__ sA) {
    const int r = blockIdx.x;
    const int tid = threadIdx.x;
    __shared__ float red[4];
    __shared__ float fsh;
    const float* s0 = sup + (size_t)r * D_SUP;
    const float* s1 = anom + (size_t)r * D_ANOM;
    const float* s2 = ind + (size_t)r * D_IND;
    float m = 0.f;
    for (int i = tid; i < D_IN; i += 128) {
        float v = (i < D_SUP) ? s0[i] : (i < D_SUP + D_ANOM) ? s1[i - D_SUP]
                                                             : s2[i - D_SUP - D_ANOM];
        m = fmaxf(m, fabsf(v));
    }
    #pragma unroll
    for (int o = 16; o; o >>= 1) m = fmaxf(m, __shfl_xor_sync(0xFFFFFFFFu, m, o));
    if ((tid & 31) == 0) red[tid >> 5] = m;
    __syncthreads();
    if (tid == 0) {
        float mm = fmaxf(fmaxf(red[0], red[1]), fmaxf(red[2], red[3]));
        mm = fmaxf(mm, 1e-30f);
        fsh = 32256.f / mm;
        sA[r] = mm / 32256.f;
    }
    __syncthreads();
    const float f = fsh;
    for (int i = tid; i < D_IN; i += 128) {
        float v = (i < D_SUP) ? s0[i] : (i < D_SUP + D_ANOM) ? s1[i - D_SUP]
                                                             : s2[i - D_SUP - D_ANOM];
        int8_t h, l;
        split16(v, f, h, l);
        Aqh[(size_t)r * D_IN + i] = h;
        Aql[(size_t)r * D_IN + i] = l;
    }
}

// ---------------- aw[b] = mean(|anomaly[b,:]|) -----------------------------
__global__ __launch_bounds__(256) void aw_kernel(const float* __restrict__ anom,
                                                 float* __restrict__ aw) {
    int warp = (blockIdx.x * blockDim.x + threadIdx.x) >> 5;
    int lane = threadIdx.x & 31;
    if (warp >= BB) return;
    float4 v = *(const float4*)(anom + (size_t)warp * D_ANOM + lane * 4);
    float s = fabsf(v.x) + fabsf(v.y) + fabsf(v.z) + fabsf(v.w);
    #pragma unroll
    for (int o = 16; o; o >>= 1) s += __shfl_xor_sync(0xFFFFFFFFu, s, o);
    if (lane == 0) aw[warp] = s * (1.0f / D_ANOM);
}

// ---------------- Mk^T hi/lo into Wfin rows 128-255 ------------------------
__global__ __launch_bounds__(256) void mkfin_kernel(const float* __restrict__ refp,
                                                    const float* __restrict__ objp,
                                                    __nv_bfloat16* __restrict__ WfH,
                                                    __nv_bfloat16* __restrict__ WfL) {
    const int k = blockIdx.x;
    __shared__ float Rs[32][FEAT];
    __shared__ float Os[32][FEAT];
    const int tid = threadIdx.x;
    const int tc = tid & 15;
    const int tr = tid >> 4;
    float acc[8][8] = {};
    const float* rb = refp + (size_t)k * CAP * FEAT;
    const float* ob = objp + (size_t)k * CAP * FEAT;
    for (int c0 = 0; c0 < CAP; c0 += 32) {
        #pragma unroll
        for (int i = tid; i < 32 * FEAT / 4; i += 256) {
            int c = i >> 5, d4 = (i & 31) * 4;
            *(float4*)&Rs[c][d4] = *(const float4*)(rb + (size_t)(c0 + c) * FEAT + d4);
            *(float4*)&Os[c][d4] = *(const float4*)(ob + (size_t)(c0 + c) * FEAT + d4);
        }
        __syncthreads();
        #pragma unroll 8
        for (int c = 0; c < 32; c++) {
            float a[8], b[8];
            #pragma unroll
            for (int i = 0; i < 8; i += 4) *(float4*)&a[i] = *(const float4*)&Rs[c][tr * 8 + i];
            #pragma unroll
            for (int j = 0; j < 8; j += 4) *(float4*)&b[j] = *(const float4*)&Os[c][tc * 8 + j];
            #pragma unroll
            for (int i = 0; i < 8; i++)
                #pragma unroll
                for (int j = 0; j < 8; j++) acc[i][j] += a[i] * b[j];
        }
        __syncthreads();
    }
    #pragma unroll
    for (int j = 0; j < 8; j++) {
        int e = tc * 8 + j;
        __nv_bfloat16 hv[8], lv[8];
        #pragma unroll
        for (int i = 0; i < 8; i++) {
            float v = acc[i][j];
            __nv_bfloat16 hi = __float2bfloat16(v);
            hv[i] = hi;
            lv[i] = __float2bfloat16(v - __bfloat162float(hi));
        }
        size_t base = (size_t)k * 256 * FEAT + (size_t)(128 + e) * FEAT + tr * 8;
        *(uint4*)(WfH + base) = *(uint4*)hv;
        *(uint4*)(WfL + base) = *(uint4*)lv;
    }
}

// ---------------- transpose + hi/lo split:  dst[n][k] = W[k][n] ------------
__global__ __launch_bounds__(256) void tsplit_kernel(const float* __restrict__ W,
                                                     __nv_bfloat16* __restrict__ Wh,
                                                     __nv_bfloat16* __restrict__ Wl,
                                                     int K, int N, int dstBatchStride) {
    const int batch = blockIdx.z;
    W += (size_t)batch * K * N;
    Wh += (size_t)batch * dstBatchStride;
    Wl += (size_t)batch * dstBatchStride;
    __shared__ float t[32][33];
    const int k0 = blockIdx.x * 32;
    const int n0 = blockIdx.y * 32;
    const int tx = threadIdx.x, ty = threadIdx.y;
    #pragma unroll
    for (int i = 0; i < 4; i++)
        t[ty + 8 * i][tx] = W[(size_t)(k0 + ty + 8 * i) * N + n0 + tx];
    __syncthreads();
    #pragma unroll
    for (int i = 0; i < 4; i++) {
        int n = n0 + ty + 8 * i;
        int k = k0 + tx;
        float v = t[tx][ty + 8 * i];
        __nv_bfloat16 hi = __float2bfloat16(v);
        __nv_bfloat16 lo = __float2bfloat16(v - __bfloat162float(hi));
        Wh[(size_t)n * K + k] = hi;
        Wl[(size_t)n * K + k] = lo;
    }
}

// ===========================================================================
// GEMM1 int8: h1 = relu(Aq @ Wq^T scaled + b1) -> bf16 hi/lo
// CTA = 128 rows x 128 cols (nhalf selects col half). 16 warps 4x4, warp 32x32.
// K chunks of 64, 2-stage cp.async. 3 int8 mma per k32 (hh, 2x cross).
// ===========================================================================
#define QROW 80        // smem row stride bytes (64 data + 16 pad)
#define QAH 0
#define QAL 10240
#define QWH 20480
#define QWL 30720
#define QBUF 40960
#define QSMEM (2 * QBUF)
#define QNIT (D_IN / 64)

__global__ __launch_bounds__(512, 1) void gemm1_q(
    const int8_t* __restrict__ Aqh, const int8_t* __restrict__ Aql,
    const int8_t* __restrict__ Wqh, const int8_t* __restrict__ Wql,
    const float* __restrict__ sA, const float* __restrict__ sW,
    const float* __restrict__ bias,
    __nv_bfloat16* __restrict__ Oh, __nv_bfloat16* __restrict__ Ol) {
    extern __shared__ char sm[];
    const uint32_t sb = smem_u32(sm);
    const int tid = threadIdx.x;
    const int wid = tid >> 5, lane = tid & 31;
    const int warpM = (wid & 3) * 32;
    const int warpN = (wid >> 2) * 32;
    const int n0 = blockIdx.x * 128;
    const int m0 = blockIdx.y * 128;

    int32_t hh[2][4][4], cr[2][4][4];
    #pragma unroll
    for (int i = 0; i < 2; i++)
        #pragma unroll
        for (int j = 0; j < 4; j++)
            #pragma unroll
            for (int q = 0; q < 4; q++) { hh[i][j][q] = 0; cr[i][j][q] = 0; }

    auto issue = [&](int it, int b) {
        const int kc0 = it * 64;
        const uint32_t bb = sb + b * QBUF;
        #pragma unroll
        for (int t = 0; t < 4; t++) {
            int idx = tid + t * 512;            // 0..2047
            if (idx < 1024) {                   // A planes
                int plane = idx >= 512;
                int cc = idx & 511;
                int row = cc >> 2, q = cc & 3;
                const int8_t* src = (plane ? Aql : Aqh) + (size_t)(m0 + row) * D_IN + kc0 + q * 16;
                cp16(bb + (plane ? QAL : QAH) + row * QROW + q * 16, src);
            } else {                            // W planes
                int j = idx - 1024;
                int plane = j >= 512;
                int cc = j & 511;
                int row = cc >> 2, q = cc & 3;
                const int8_t* src = (plane ? Wql : Wqh) + (size_t)(n0 + row) * D_IN + kc0 + q * 16;
                cp16(bb + (plane ? QWL : QWH) + row * QROW + q * 16, src);
            }
        }
        CP_COMMIT();
    };

    issue(0, 0);

    for (int it = 0; it < QNIT; it++) {
        const int b = it & 1;
        const uint32_t bb = sb + b * QBUF;
        CP_WAIT0();
        __syncthreads();
        if (it + 1 < QNIT) issue(it + 1, b ^ 1);

        #pragma unroll
        for (int kq = 0; kq < 2; kq++) {
            const uint32_t koff = kq * 32 + ((lane >> 4) << 4);
            uint32_t a_h[2][4], a_l[2][4], bh[4][2], bl[4][2];
            #pragma unroll
            for (int mt = 0; mt < 2; mt++) {
                uint32_t off = (uint32_t)(warpM + mt * 16 + (lane & 15)) * QROW + koff;
                ldsm4(a_h[mt], bb + QAH + off);
                ldsm4(a_l[mt], bb + QAL + off);
            }
            #pragma unroll
            for (int nt2 = 0; nt2 < 2; nt2++) {
                uint32_t off = (uint32_t)(warpN + nt2 * 16 + (lane & 15)) * QROW + koff;
                uint32_t r[4];
                ldsm4(r, bb + QWH + off);
                bh[2 * nt2][0] = r[0]; bh[2 * nt2][1] = r[2];
                bh[2 * nt2 + 1][0] = r[1]; bh[2 * nt2 + 1][1] = r[3];
                ldsm4(r, bb + QWL + off);
                bl[2 * nt2][0] = r[0]; bl[2 * nt2][1] = r[2];
                bl[2 * nt2 + 1][0] = r[1]; bl[2 * nt2 + 1][1] = r[3];
            }
            #pragma unroll
            for (int mt = 0; mt < 2; mt++)
                #pragma unroll
                for (int nt = 0; nt < 4; nt++) {
                    mma_s8(hh[mt][nt], a_h[mt], bh[nt]);
                    mma_s8(cr[mt][nt], a_h[mt], bl[nt]);
                    mma_s8(cr[mt][nt], a_l[mt], bh[nt]);
                }
        }
    }

    // epilogue: D = (hh*256 + cr) * 256 * sA[row] * sW[col]; +bias, relu, bf16 split
    #pragma unroll
    for (int mt = 0; mt < 2; mt++) {
        const int r1 = m0 + warpM + mt * 16 + (lane >> 2);
        const float fa1 = 256.f * sA[r1];
        const float fa2 = 256.f * sA[r1 + 8];
        #pragma unroll
        for (int nt = 0; nt < 4; nt++) {
            const int ng = n0 + warpN + nt * 8 + ((lane & 3) << 1);
            float2 sw2 = *(const float2*)(sW + ng);
            float2 bv = *(const float2*)(bias + ng);
            float v00 = fmaf(256.f, (float)hh[mt][nt][0], (float)cr[mt][nt][0]) * fa1 * sw2.x + bv.x;
            float v01 = fmaf(256.f, (float)hh[mt][nt][1], (float)cr[mt][nt][1]) * fa1 * sw2.y + bv.y;
            float v10 = fmaf(256.f, (float)hh[mt][nt][2], (float)cr[mt][nt][2]) * fa2 * sw2.x + bv.x;
            float v11 = fmaf(256.f, (float)hh[mt][nt][3], (float)cr[mt][nt][3]) * fa2 * sw2.y + bv.y;
            v00 = fmaxf(v00, 0.f); v01 = fmaxf(v01, 0.f);
            v10 = fmaxf(v10, 0.f); v11 = fmaxf(v11, 0.f);
            __nv_bfloat16 h00 = __float2bfloat16(v00), h01 = __float2bfloat16(v01);
            __nv_bfloat16 h10 = __float2bfloat16(v10), h11 = __float2bfloat16(v11);
            __nv_bfloat162 hi0 = {h00, h01}, hi1 = {h10, h11};
            __nv_bfloat162 lo0 = __floats2bfloat162_rn(v00 - __bfloat162float(h00),
                                                       v01 - __bfloat162float(h01));
            __nv_bfloat162 lo1 = __floats2bfloat162_rn(v10 - __bfloat162float(h10),
                                                       v11 - __bfloat162float(h11));
            *(__nv_bfloat162*)(Oh + (size_t)r1 * H1 + ng) = hi0;
            *(__nv_bfloat162*)(Ol + (size_t)r1 * H1 + ng) = lo0;
            *(__nv_bfloat162*)(Oh + (size_t)(r1 + 8) * H1 + ng) = hi1;
            *(__nv_bfloat162*)(Ol + (size_t)(r1 + 8) * H1 + ng) = lo1;
        }
    }
}

// ===========================================================================
// Fused tail (unchanged from R6): GEMM2 + 12 layers + final retrieval.
// ===========================================================================
#define LDA 136
#define TAIL_SMEM ((128 * LDA * 2 + 256 * LDA * 2) * 2 + 256 * 4)

__global__ __launch_bounds__(512, 1) void fused_tail(
    const __nv_bfloat16* __restrict__ h1h, const __nv_bfloat16* __restrict__ h1l,
    const __nv_bfloat16* __restrict__ Wh2, const __nv_bfloat16* __restrict__ Wl2,
    const float* __restrict__ b2,
    const __nv_bfloat16* __restrict__ WhC, const __nv_bfloat16* __restrict__ WlC,
    const float* __restrict__ consB,
    const __nv_bfloat16* __restrict__ WfH, const __nv_bfloat16* __restrict__ WfL,
    const float* __restrict__ retB, const float* __restrict__ aw,
    float* __restrict__ out) {
    extern __shared__ __nv_bfloat16 smt[];
    __nv_bfloat16* sAh = smt;
    __nv_bfloat16* sAl = sAh + 128 * LDA;
    __nv_bfloat16* sWh = sAl + 128 * LDA;
    __nv_bfloat16* sWl = sWh + 256 * LDA;
    float* wsum = (float*)(sWl + 256 * LDA);
    float* saw  = wsum + 128;

    const int tid = threadIdx.x;
    const int wid = tid >> 5, lane = tid & 31;
    const int wm = wid & 3;
    const int wn = wid >> 2;
    const int m0 = blockIdx.x * 128;

    const uint32_t aAh = smem_u32(sAh), aAl = smem_u32(sAl);
    const uint32_t aWh = smem_u32(sWh), aWl = smem_u32(sWl);

    auto issueW = [&](const __nv_bfloat16* srcH, const __nv_bfloat16* srcL,
                      int srcStride, int slot) {
        #pragma unroll
        for (int t = 0; t < 8; t++) {
            int idx = tid + t * 512;
            int half = idx >= 2048;
            int cc = idx & 2047;
            int row = cc >> 4, q = cc & 15;
            const __nv_bfloat16* src = (half ? srcL : srcH) + (size_t)row * srcStride + q * 8;
            cp16((half ? aWl : aWh) + (uint32_t)((slot * 128 + row) * LDA + q * 8) * 2, src);
        }
        CP_COMMIT();
    };
    auto issueAct = [&](int kc) {
        #pragma unroll
        for (int t = 0; t < 8; t++) {
            int idx = tid + t * 512;
            int half = idx >= 2048;
            int cc = idx & 2047;
            int row = cc >> 4, q = cc & 15;
            const __nv_bfloat16* src = (half ? h1l : h1h)
                + (size_t)(m0 + row) * H1 + kc * 128 + q * 8;
            cp16((half ? aAl : aAh) + (uint32_t)(row * LDA + q * 8) * 2, src);
        }
        CP_COMMIT();
    };
    auto issueFin = [&](int k) {
        #pragma unroll
        for (int t = 0; t < 16; t++) {
            int idx = tid + t * 512;
            int half = idx >= 4096;
            int cc = idx & 4095;
            int row = cc >> 4, q = cc & 15;
            const __nv_bfloat16* src = (half ? WfL : WfH)
                + (size_t)k * 256 * FEAT + (size_t)row * FEAT + q * 8;
            cp16((half ? aWl : aWh) + (uint32_t)(row * LDA + q * 8) * 2, src);
        }
        CP_COMMIT();
    };

    auto mma128 = [&](float acc4[2][4][4], int slot) {
        const uint32_t base = (uint32_t)(slot * 128 * LDA) * 2;
        #pragma unroll
        for (int ch = 0; ch < 8; ch++) {
            const int colh = ch * 16 + ((lane >> 4) << 3);
            uint32_t a_h[2][4], a_l[2][4], bfr[4][2];
            #pragma unroll
            for (int mt = 0; mt < 2; mt++) {
                int row = wm * 32 + mt * 16 + (lane & 15);
                ldsm4(a_h[mt], aAh + (uint32_t)(row * LDA + colh) * 2);
                ldsm4(a_l[mt], aAl + (uint32_t)(row * LDA + colh) * 2);
            }
            #pragma unroll
            for (int nt2 = 0; nt2 < 2; nt2++) {
                int row = wn * 32 + nt2 * 16 + (lane & 15);
                uint32_t r[4];
                ldsm4(r, aWh + base + (uint32_t)(row * LDA + colh) * 2);
                bfr[2 * nt2][0] = r[0]; bfr[2 * nt2][1] = r[2];
                bfr[2 * nt2 + 1][0] = r[1]; bfr[2 * nt2 + 1][1] = r[3];
            }
            #pragma unroll
            for (int mt = 0; mt < 2; mt++)
                #pragma unroll
                for (int nt = 0; nt < 4; nt++) mma_bf16(acc4[mt][nt], a_h[mt], bfr[nt]);
            #pragma unroll
            for (int mt = 0; mt < 2; mt++)
                #pragma unroll
                for (int nt = 0; nt < 4; nt++) mma_bf16(acc4[mt][nt], a_l[mt], bfr[nt]);
            #pragma unroll
            for (int nt2 = 0; nt2 < 2; nt2++) {
                int row = wn * 32 + nt2 * 16 + (lane & 15);
                uint32_t r[4];
                ldsm4(r, aWl + base + (uint32_t)(row * LDA + colh) * 2);
                bfr[2 * nt2][0] = r[0]; bfr[2 * nt2][1] = r[2];
                bfr[2 * nt2 + 1][0] = r[1]; bfr[2 * nt2 + 1][1] = r[3];
            }
            #pragma unroll
            for (int mt = 0; mt < 2; mt++)
                #pragma unroll
                for (int nt = 0; nt < 4; nt++) mma_bf16(acc4[mt][nt], a_h[mt], bfr[nt]);
        }
    };
    auto epilogue = [&](float acc4[2][4][4], const float* biasp) {
        #pragma unroll
        for (int mt = 0; mt < 2; mt++) {
            const int row = wm * 32 + mt * 16 + (lane >> 2);
            #pragma unroll
            for (int nt = 0; nt < 4; nt++) {
                const int col = wn * 32 + nt * 8 + ((lane & 3) << 1);
                float2 bv = *(const float2*)(biasp + col);
                float v00 = fmaxf(acc4[mt][nt][0] + bv.x, 0.f);
                float v01 = fmaxf(acc4[mt][nt][1] + bv.y, 0.f);
                float v10 = fmaxf(acc4[mt][nt][2] + bv.x, 0.f);
                float v11 = fmaxf(acc4[mt][nt][3] + bv.y, 0.f);
                __nv_bfloat16 h00 = __float2bfloat16(v00), h01 = __float2bfloat16(v01);
                __nv_bfloat16 h10 = __float2bfloat16(v10), h11 = __float2bfloat16(v11);
                __nv_bfloat162 hi0 = {h00, h01}, hi1 = {h10, h11};
                __nv_bfloat162 lo0 = __floats2bfloat162_rn(v00 - __bfloat162float(h00),
                                                           v01 - __bfloat162float(h01));
                __nv_bfloat162 lo1 = __floats2bfloat162_rn(v10 - __bfloat162float(h10),
                                                           v11 - __bfloat162float(h11));
                *(__nv_bfloat162*)(sAh + row * LDA + col) = hi0;
                *(__nv_bfloat162*)(sAl + row * LDA + col) = lo0;
                *(__nv_bfloat162*)(sAh + (row + 8) * LDA + col) = hi1;
                *(__nv_bfloat162*)(sAl + (row + 8) * LDA + col) = lo1;
            }
        }
    };

    if (tid < 128) saw[tid] = aw[m0 + tid];

    issueW(Wh2, Wl2, H1, 0);
    issueAct(0);
    {
        #pragma unroll
        for (int t = 0; t < 8; t++) {
            int idx = tid + t * 512;
            int half = idx >= 2048;
            int cc = idx & 2047;
            int row = cc >> 4, q = cc & 15;
            const __nv_bfloat16* src = (half ? Wl2 : Wh2) + (size_t)row * H1 + 128 + q * 8;
            cp16((half ? aWl : aWh) + (uint32_t)((128 + row) * LDA + q * 8) * 2, src);
        }
        CP_COMMIT();
    }

    float acc4[2][4][4];
    #pragma unroll
    for (int i = 0; i < 2; i++)
        #pragma unroll
        for (int j = 0; j < 4; j++)
            #pragma unroll
            for (int q = 0; q < 4; q++) acc4[i][j][q] = 0.f;

    CP_WAIT1();
    __syncthreads();
    mma128(acc4, 0);
    __syncthreads();
    issueAct(1);
    issueW(WhC, WlC, FEAT, 0);
    CP_WAIT1();
    __syncthreads();
    mma128(acc4, 1);
    __syncthreads();
    epilogue(acc4, b2);
    __syncthreads();

    for (int l = 0; l < DEPTH; l++) {
        if (l + 1 < DEPTH)
            issueW(WhC + (size_t)(l + 1) * FEAT * FEAT,
                   WlC + (size_t)(l + 1) * FEAT * FEAT, FEAT, (l + 1) & 1);
        if (l + 1 < DEPTH) { CP_WAIT1(); } else { CP_WAIT0(); }
        __syncthreads();
        #pragma unroll
        for (int i = 0; i < 2; i++)
            #pragma unroll
            for (int j = 0; j < 4; j++)
                #pragma unroll
                for (int q = 0; q < 4; q++) acc4[i][j][q] = 0.f;
        mma128(acc4, l & 1);
        __syncthreads();
        epilogue(acc4, consB + (size_t)l * FEAT);
        __syncthreads();
    }

    issueFin(0);
    CP_WAIT0();
    const float cfac = 0.42f * 1.8f / (float)CAP;
    for (int k = 0; k < NCOND; k++) {
        __syncthreads();
        if (tid < 128) wsum[tid] = 0.f;

        float acc8[2][8][4];
        #pragma unroll
        for (int i = 0; i < 2; i++)
            #pragma unroll
            for (int j = 0; j < 8; j++)
                #pragma unroll
                for (int q = 0; q < 4; q++) acc8[i][j][q] = 0.f;

        #pragma unroll
        for (int ch = 0; ch < 8; ch++) {
            const int colh = ch * 16 + ((lane >> 4) << 3);
            uint32_t a_h[2][4], a_l[2][4], bfr[8][2];
            #pragma unroll
            for (int mt = 0; mt < 2; mt++) {
                int row = wm * 32 + mt * 16 + (lane & 15);
                ldsm4(a_h[mt], aAh + (uint32_t)(row * LDA + colh) * 2);
                ldsm4(a_l[mt], aAl + (uint32_t)(row * LDA + colh) * 2);
            }
            #pragma unroll
            for (int nt2 = 0; nt2 < 4; nt2++) {
                int row = wn * 64 + nt2 * 16 + (lane & 15);
                uint32_t r[4];
                ldsm4(r, aWh + (uint32_t)(row * LDA + colh) * 2);
                bfr[2 * nt2][0] = r[0]; bfr[2 * nt2][1] = r[2];
                bfr[2 * nt2 + 1][0] = r[1]; bfr[2 * nt2 + 1][1] = r[3];
            }
            #pragma unroll
            for (int mt = 0; mt < 2; mt++)
                #pragma unroll
                for (int nt = 0; nt < 8; nt++) mma_bf16(acc8[mt][nt], a_h[mt], bfr[nt]);
            #pragma unroll
            for (int mt = 0; mt < 2; mt++)
                #pragma unroll
                for (int nt = 0; nt < 8; nt++) mma_bf16(acc8[mt][nt], a_l[mt], bfr[nt]);
            #pragma unroll
            for (int nt2 = 0; nt2 < 4; nt2++) {
                int row = wn * 64 + nt2 * 16 + (lane & 15);
                uint32_t r[4];
                ldsm4(r, aWl + (uint32_t)(row * LDA + colh) * 2);
                bfr[2 * nt2][0] = r[0]; bfr[2 * nt2][1] = r[2];
                bfr[2 * nt2 + 1][0] = r[1]; bfr[2 * nt2 + 1][1] = r[3];
            }
            #pragma unroll
            for (int mt = 0; mt < 2; mt++)
                #pragma unroll
                for (int nt = 0; nt < 8; nt++) mma_bf16(acc8[mt][nt], a_h[mt], bfr[nt]);
        }
        __syncthreads();
        if (k + 1 < NCOND) issueFin(k + 1);

        if (wn >= 2) {
            #pragma unroll
            for (int mt = 0; mt < 2; mt++) {
                const int r1 = wm * 32 + mt * 16 + (lane >> 2);
                float p1 = 0.f, p2 = 0.f;
                #pragma unroll
                for (int nt = 0; nt < 8; nt++) {
                    const int e0 = (wn - 2) * 64 + nt * 8 + ((lane & 3) << 1);
                    float m00 = __bfloat162float(sAh[r1 * LDA + e0]) +
                                __bfloat162float(sAl[r1 * LDA + e0]);
                    float m01 = __bfloat162float(sAh[r1 * LDA + e0 + 1]) +
                                __bfloat162float(sAl[r1 * LDA + e0 + 1]);
                    float m10 = __bfloat162float(sAh[(r1 + 8) * LDA + e0]) +
                                __bfloat162float(sAl[(r1 + 8) * LDA + e0]);
                    float m11 = __bfloat162float(sAh[(r1 + 8) * LDA + e0 + 1]) +
                                __bfloat162float(sAl[(r1 + 8) * LDA + e0 + 1]);
                    p1 += acc8[mt][nt][0] * m00 + acc8[mt][nt][1] * m01;
                    p2 += acc8[mt][nt][2] * m10 + acc8[mt][nt][3] * m11;
                }
                atomicAdd(&wsum[r1], p1);
                atomicAdd(&wsum[r1 + 8], p2);
            }
        }
        __syncthreads();
        if (tid < 128) wsum[tid] = wsum[tid] * cfac + 0.3f * saw[tid];
        __syncthreads();

        if (wn < 2) {
            #pragma unroll
            for (int mt = 0; mt < 2; mt++) {
                const int rl = wm * 32 + mt * 16 + (lane >> 2);
                const float w1 = wsum[rl], w2 = wsum[rl + 8];
                #pragma unroll
                for (int nt = 0; nt < 8; nt++) {
                    const int col = wn * 64 + nt * 8 + ((lane & 3) << 1);
                    float2 bv = *(const float2*)(retB + (size_t)k * FEAT + col);
                    size_t base1 = (size_t)(m0 + rl) * (NCOND * FEAT) + (size_t)k * FEAT + col;
                    size_t base2 = (size_t)(m0 + rl + 8) * (NCOND * FEAT) + (size_t)k * FEAT + col;
                    *(float2*)(out + base1) = make_float2((acc8[mt][nt][0] + bv.x) * w1,
                                                          (acc8[mt][nt][1] + bv.y) * w1);
                    *(float2*)(out + base2) = make_float2((acc8[mt][nt][2] + bv.x) * w2,
                                                          (acc8[mt][nt][3] + bv.y) * w2);
                }
            }
        }
        if (k + 1 < NCOND) CP_WAIT0();
    }
}

// ===========================================================================
extern "C" void kernel_launch(void* const* d_in, const int* in_sizes, int n_in,
                              void* d_out, int out_size) {
    const float* sup  = (const float*)d_in[0];
    const float* anom = (const float*)d_in[1];
    const float* ind  = (const float*)d_in[2];
    const float* ipW1 = (const float*)d_in[3];
    const float* ipb1 = (const float*)d_in[4];
    const float* ipW2 = (const float*)d_in[5];
    const float* ipb2 = (const float*)d_in[6];
    const float* consW = (const float*)d_in[7];
    const float* consB = (const float*)d_in[8];
    const float* refp = (const float*)d_in[9];
    const float* objp = (const float*)d_in[10];
    const float* retW = (const float*)d_in[11];
    const float* retB = (const float*)d_in[12];
    float* out = (float*)d_out;

    int8_t *Aqh, *Aql, *Wqh, *Wql;
    __nv_bfloat16 *Wh2, *Wl2, *WhC, *WlC, *h1h, *h1l, *WfH, *WfL;
    float *aw, *sA, *sW;
    cudaGetSymbolAddress((void**)&Aqh, g_Aqh);
    cudaGetSymbolAddress((void**)&Aql, g_Aql);
    cudaGetSymbolAddress((void**)&Wqh, g_Wqh);
    cudaGetSymbolAddress((void**)&Wql, g_Wql);
    cudaGetSymbolAddress((void**)&sA, g_sA);
    cudaGetSymbolAddress((void**)&sW, g_sW);
    cudaGetSymbolAddress((void**)&Wh2, g_Wh2);
    cudaGetSymbolAddress((void**)&Wl2, g_Wl2);
    cudaGetSymbolAddress((void**)&WhC, g_WhC);
    cudaGetSymbolAddress((void**)&WlC, g_WlC);
    cudaGetSymbolAddress((void**)&h1h, g_h1h);
    cudaGetSymbolAddress((void**)&h1l, g_h1l);
    cudaGetSymbolAddress((void**)&WfH, g_WfinH);
    cudaGetSymbolAddress((void**)&WfL, g_WfinL);
    cudaGetSymbolAddress((void**)&aw, g_aw);

    cudaFuncSetAttribute(gemm1_q, cudaFuncAttributeMaxDynamicSharedMemorySize, QSMEM);
    cudaFuncSetAttribute(fused_tail, cudaFuncAttributeMaxDynamicSharedMemorySize, TAIL_SMEM);

    // launch order chosen so gemm1_q is the 6th launch (ncu -s 5 -c 1 capture)
    quantW_kernel<<<H1, 128>>>(ipW1, Wqh, Wql, sW);                                   // 1
    quantA_kernel<<<BB, 128>>>(sup, anom, ind, Aqh, Aql, sA);                         // 2
    aw_kernel<<<BB * 32 / 256, 256>>>(anom, aw);                                      // 3
    mkfin_kernel<<<NCOND, 256>>>(refp, objp, WfH, WfL);                               // 4
    tsplit_kernel<<<dim3(H1 / 32, FEAT / 32, 1), dim3(32, 8)>>>(ipW2, Wh2, Wl2, H1, FEAT, FEAT * H1); // 5
    gemm1_q<<<dim3(2, BB / 128), 512, QSMEM>>>(Aqh, Aql, Wqh, Wql, sA, sW, ipb1, h1h, h1l);           // 6 (profiled)
    tsplit_kernel<<<dim3(FEAT / 32, FEAT / 32, DEPTH), dim3(32, 8)>>>(consW, WhC, WlC, FEAT, FEAT, FEAT * FEAT); // 7
    tsplit_kernel<<<dim3(FEAT / 32, FEAT / 32, NCOND), dim3(32, 8)>>>(retW, WfH, WfL, FEAT, FEAT, 256 * FEAT);   // 8
    fused_tail<<<BB / 128, 512, TAIL_SMEM>>>(
        h1h, h1l, Wh2, Wl2, ipb2, WhC, WlC, consB, WfH, WfL, retB, aw, out);          // 9
}

// round 9
// speedup vs baseline: 1.0019x; 1.0019x over previous
#include <cuda_runtime.h>
#include <cuda_bf16.h>
#include <stdint.h>

#define BB 16384
#define D_SUP 1024
#define D_ANOM 128
#define D_IND 2048
#define D_IN 3200
#define H1 256
#define FEAT 128
#define DEPTH 12
#define NCOND 14
#define CAP 256

// ---------------- scratch (device globals; no allocation allowed) ----------
__device__ int8_t g_Aqh[BB * D_IN];                  // A hi plane [16384][3200]
__device__ int8_t g_Aql[BB * D_IN];                  // A lo plane
__device__ int8_t g_Wqh[H1 * D_IN];                  // W1^T hi plane [256][3200]
__device__ int8_t g_Wql[H1 * D_IN];
__device__ float g_sA[BB];                           // rowmax/32256
__device__ float g_sW[H1];                           // colmax/32256
__device__ __nv_bfloat16 g_Wh2[FEAT * H1];           // W2^T hi [128][256]
__device__ __nv_bfloat16 g_Wl2[FEAT * H1];
__device__ __nv_bfloat16 g_WhC[DEPTH * FEAT * FEAT]; // consW^T hi [12][128][128]
__device__ __nv_bfloat16 g_WlC[DEPTH * FEAT * FEAT];
__device__ __nv_bfloat16 g_h1h[BB * H1];             // h1 hi/lo [16384][256]
__device__ __nv_bfloat16 g_h1l[BB * H1];
__device__ __nv_bfloat16 g_WfinH[NCOND * 256 * FEAT]; // [k][256][128]: rows 0-127 retW^T, 128-255 Mk^T
__device__ __nv_bfloat16 g_WfinL[NCOND * 256 * FEAT];
__device__ float g_aw[BB];

// ---------------- helpers --------------------------------------------------
__device__ __forceinline__ uint32_t smem_u32(const void* p) {
    uint32_t a;
    asm("{ .reg .u64 t; cvta.to.shared.u64 t, %1; cvt.u32.u64 %0, t; }" : "=r"(a) : "l"(p));
    return a;
}
__device__ __forceinline__ void ldsm4(uint32_t* r, uint32_t addr) {
    asm volatile("ldmatrix.sync.aligned.m8n8.x4.shared.b16 {%0,%1,%2,%3}, [%4];"
                 : "=r"(r[0]), "=r"(r[1]), "=r"(r[2]), "=r"(r[3]) : "r"(addr));
}
__device__ __forceinline__ void mma_bf16(float* c, const uint32_t* a, const uint32_t* b) {
    asm volatile("mma.sync.aligned.m16n8k16.row.col.f32.bf16.bf16.f32 "
                 "{%0,%1,%2,%3}, {%4,%5,%6,%7}, {%8,%9}, {%0,%1,%2,%3};"
                 : "+f"(c[0]), "+f"(c[1]), "+f"(c[2]), "+f"(c[3])
                 : "r"(a[0]), "r"(a[1]), "r"(a[2]), "r"(a[3]), "r"(b[0]), "r"(b[1]));
}
__device__ __forceinline__ void mma_s8(int32_t* c, const uint32_t* a, const uint32_t* b) {
    asm volatile("mma.sync.aligned.m16n8k32.row.col.s32.s8.s8.s32 "
                 "{%0,%1,%2,%3}, {%4,%5,%6,%7}, {%8,%9}, {%0,%1,%2,%3};"
                 : "+r"(c[0]), "+r"(c[1]), "+r"(c[2]), "+r"(c[3])
                 : "r"(a[0]), "r"(a[1]), "r"(a[2]), "r"(a[3]), "r"(b[0]), "r"(b[1]));
}
__device__ __forceinline__ void cp16(uint32_t smem, const void* g) {
    asm volatile("cp.async.cg.shared.global [%0], [%1], 16;" :: "r"(smem), "l"(g));
}
#define CP_COMMIT() asm volatile("cp.async.commit_group;" ::: "memory")
#define CP_WAIT0()  asm volatile("cp.async.wait_group 0;" ::: "memory")
#define CP_WAIT1()  asm volatile("cp.async.wait_group 1;" ::: "memory")

// fixed-point split of qx (|qx| <= 32256) into hi/lo int8
__device__ __forceinline__ void split16(float x, float f, int8_t& h, int8_t& l) {
    int qx = (int)rintf(x * f);
    int hi = (qx + 128) >> 8;
    h = (int8_t)hi;
    l = (int8_t)(qx - (hi << 8));
}

// ---------------- quantW: W1 [3200][256] -> int8 planes [256][3200] + scale
__global__ __launch_bounds__(128) void quantW_kernel(const float* __restrict__ W1,
                                                     int8_t* __restrict__ Wqh,
                                                     int8_t* __restrict__ Wql,
                                                     float* __restrict__ sW) {
    const int n = blockIdx.x;
    const int tid = threadIdx.x;
    __shared__ float red[4];
    __shared__ float fsh;
    float m = 0.f;
    for (int k = tid; k < D_IN; k += 128)
        m = fmaxf(m, fabsf(W1[(size_t)k * H1 + n]));
    #pragma unroll
    for (int o = 16; o; o >>= 1) m = fmaxf(m, __shfl_xor_sync(0xFFFFFFFFu, m, o));
    if ((tid & 31) == 0) red[tid >> 5] = m;
    __syncthreads();
    if (tid == 0) {
        float mm = fmaxf(fmaxf(red[0], red[1]), fmaxf(red[2], red[3]));
        mm = fmaxf(mm, 1e-30f);
        fsh = 32256.f / mm;
        sW[n] = mm / 32256.f;
    }
    __syncthreads();
    const float f = fsh;
    for (int k = tid; k < D_IN; k += 128) {
        int8_t h, l;
        split16(W1[(size_t)k * H1 + n], f, h, l);
        Wqh[(size_t)n * D_IN + k] = h;
        Wql[(size_t)n * D_IN + k] = l;
    }
}

// ---------------- quantA: concat(sup,anom,ind) row -> int8 planes + scale ---
__global__ __launch_bounds__(128) void quantA_kernel(const float* __restrict__ sup,
                                                     const float* __restrict__ anom,
                                                     const float* __restrict__ ind,
                                                     int8_t* __restrict__ Aqh,
                                                     int8_t* __restrict__ Aql,
                                                     float* __restrict__ sA) {
    const int r = blockIdx.x;
    const int tid = threadIdx.x;
    __shared__ float red[4];
    __shared__ float fsh;
    const float* s0 = sup + (size_t)r * D_SUP;
    const float* s1 = anom + (size_t)r * D_ANOM;
    const float* s2 = ind + (size_t)r * D_IND;
    float m = 0.f;
    for (int i = tid; i < D_IN; i += 128) {
        float v = (i < D_SUP) ? s0[i] : (i < D_SUP + D_ANOM) ? s1[i - D_SUP]
                                                             : s2[i - D_SUP - D_ANOM];
        m = fmaxf(m, fabsf(v));
    }
    #pragma unroll
    for (int o = 16; o; o >>= 1) m = fmaxf(m, __shfl_xor_sync(0xFFFFFFFFu, m, o));
    if ((tid & 31) == 0) red[tid >> 5] = m;
    __syncthreads();
    if (tid == 0) {
        float mm = fmaxf(fmaxf(red[0], red[1]), fmaxf(red[2], red[3]));
        mm = fmaxf(mm, 1e-30f);
        fsh = 32256.f / mm;
        sA[r] = mm / 32256.f;
    }
    __syncthreads();
    const float f = fsh;
    for (int i = tid; i < D_IN; i += 128) {
        float v = (i < D_SUP) ? s0[i] : (i < D_SUP + D_ANOM) ? s1[i - D_SUP]
                                                             : s2[i - D_SUP - D_ANOM];
        int8_t h, l;
        split16(v, f, h, l);
        Aqh[(size_t)r * D_IN + i] = h;
        Aql[(size_t)r * D_IN + i] = l;
    }
}

// ---------------- aw[b] = mean(|anomaly[b,:]|) -----------------------------
__global__ __launch_bounds__(256) void aw_kernel(const float* __restrict__ anom,
                                                 float* __restrict__ aw) {
    int warp = (blockIdx.x * blockDim.x + threadIdx.x) >> 5;
    int lane = threadIdx.x & 31;
    if (warp >= BB) return;
    float4 v = *(const float4*)(anom + (size_t)warp * D_ANOM + lane * 4);
    float s = fabsf(v.x) + fabsf(v.y) + fabsf(v.z) + fabsf(v.w);
    #pragma unroll
    for (int o = 16; o; o >>= 1) s += __shfl_xor_sync(0xFFFFFFFFu, s, o);
    if (lane == 0) aw[warp] = s * (1.0f / D_ANOM);
}

// ---------------- Mk^T hi/lo into Wfin rows 128-255 ------------------------
__global__ __launch_bounds__(256) void mkfin_kernel(const float* __restrict__ refp,
                                                    const float* __restrict__ objp,
                                                    __nv_bfloat16* __restrict__ WfH,
                                                    __nv_bfloat16* __restrict__ WfL) {
    const int k = blockIdx.x;
    __shared__ float Rs[32][FEAT];
    __shared__ float Os[32][FEAT];
    const int tid = threadIdx.x;
    const int tc = tid & 15;
    const int tr = tid >> 4;
    float acc[8][8] = {};
    const float* rb = refp + (size_t)k * CAP * FEAT;
    const float* ob = objp + (size_t)k * CAP * FEAT;
    for (int c0 = 0; c0 < CAP; c0 += 32) {
        #pragma unroll
        for (int i = tid; i < 32 * FEAT / 4; i += 256) {
            int c = i >> 5, d4 = (i & 31) * 4;
            *(float4*)&Rs[c][d4] = *(const float4*)(rb + (size_t)(c0 + c) * FEAT + d4);
            *(float4*)&Os[c][d4] = *(const float4*)(ob + (size_t)(c0 + c) * FEAT + d4);
        }
        __syncthreads();
        #pragma unroll 8
        for (int c = 0; c < 32; c++) {
            float a[8], b[8];
            #pragma unroll
            for (int i = 0; i < 8; i += 4) *(float4*)&a[i] = *(const float4*)&Rs[c][tr * 8 + i];
            #pragma unroll
            for (int j = 0; j < 8; j += 4) *(float4*)&b[j] = *(const float4*)&Os[c][tc * 8 + j];
            #pragma unroll
            for (int i = 0; i < 8; i++)
                #pragma unroll
                for (int j = 0; j < 8; j++) acc[i][j] += a[i] * b[j];
        }
        __syncthreads();
    }
    #pragma unroll
    for (int j = 0; j < 8; j++) {
        int e = tc * 8 + j;
        __nv_bfloat16 hv[8], lv[8];
        #pragma unroll
        for (int i = 0; i < 8; i++) {
            float v = acc[i][j];
            __nv_bfloat16 hi = __float2bfloat16(v);
            hv[i] = hi;
            lv[i] = __float2bfloat16(v - __bfloat162float(hi));
        }
        size_t base = (size_t)k * 256 * FEAT + (size_t)(128 + e) * FEAT + tr * 8;
        *(uint4*)(WfH + base) = *(uint4*)hv;
        *(uint4*)(WfL + base) = *(uint4*)lv;
    }
}

// ---------------- transpose + hi/lo split:  dst[n][k] = W[k][n] ------------
__global__ __launch_bounds__(256) void tsplit_kernel(const float* __restrict__ W,
                                                     __nv_bfloat16* __restrict__ Wh,
                                                     __nv_bfloat16* __restrict__ Wl,
                                                     int K, int N, int dstBatchStride) {
    const int batch = blockIdx.z;
    W += (size_t)batch * K * N;
    Wh += (size_t)batch * dstBatchStride;
    Wl += (size_t)batch * dstBatchStride;
    __shared__ float t[32][33];
    const int k0 = blockIdx.x * 32;
    const int n0 = blockIdx.y * 32;
    const int tx = threadIdx.x, ty = threadIdx.y;
    #pragma unroll
    for (int i = 0; i < 4; i++)
        t[ty + 8 * i][tx] = W[(size_t)(k0 + ty + 8 * i) * N + n0 + tx];
    __syncthreads();
    #pragma unroll
    for (int i = 0; i < 4; i++) {
        int n = n0 + ty + 8 * i;
        int k = k0 + tx;
        float v = t[tx][ty + 8 * i];
        __nv_bfloat16 hi = __float2bfloat16(v);
        __nv_bfloat16 lo = __float2bfloat16(v - __bfloat162float(hi));
        Wh[(size_t)n * K + k] = hi;
        Wl[(size_t)n * K + k] = lo;
    }
}

// ===========================================================================
// GEMM1 int8: h1 = relu(Aq @ Wq^T scaled + b1) -> bf16 hi/lo
// CTA = 128 rows x 128 cols (nhalf selects col half). 16 warps 4x4, warp 32x32.
// K chunks of 64, 2-stage cp.async. 3 int8 mma per k32 (hh, 2x cross).
// ===========================================================================
#define QROW 80        // smem row stride bytes (64 data + 16 pad)
#define QAH 0
#define QAL 10240
#define QWH 20480
#define QWL 30720
#define QBUF 40960
#define QSMEM (2 * QBUF)
#define QNIT (D_IN / 64)

__global__ __launch_bounds__(512, 1) void gemm1_q(
    const int8_t* __restrict__ Aqh, const int8_t* __restrict__ Aql,
    const int8_t* __restrict__ Wqh, const int8_t* __restrict__ Wql,
    const float* __restrict__ sA, const float* __restrict__ sW,
    const float* __restrict__ bias,
    __nv_bfloat16* __restrict__ Oh, __nv_bfloat16* __restrict__ Ol) {
    extern __shared__ char sm[];
    const uint32_t sb = smem_u32(sm);
    const int tid = threadIdx.x;
    const int wid = tid >> 5, lane = tid & 31;
    const int warpM = (wid & 3) * 32;
    const int warpN = (wid >> 2) * 32;
    const int n0 = blockIdx.x * 128;
    const int m0 = blockIdx.y * 128;

    int32_t hh[2][4][4], cr[2][4][4];
    #pragma unroll
    for (int i = 0; i < 2; i++)
        #pragma unroll
        for (int j = 0; j < 4; j++)
            #pragma unroll
            for (int q = 0; q < 4; q++) { hh[i][j][q] = 0; cr[i][j][q] = 0; }

    auto issue = [&](int it, int b) {
        const int kc0 = it * 64;
        const uint32_t bb = sb + b * QBUF;
        #pragma unroll
        for (int t = 0; t < 4; t++) {
            int idx = tid + t * 512;            // 0..2047
            if (idx < 1024) {                   // A planes
                int plane = idx >= 512;
                int cc = idx & 511;
                int row = cc >> 2, q = cc & 3;
                const int8_t* src = (plane ? Aql : Aqh) + (size_t)(m0 + row) * D_IN + kc0 + q * 16;
                cp16(bb + (plane ? QAL : QAH) + row * QROW + q * 16, src);
            } else {                            // W planes
                int j = idx - 1024;
                int plane = j >= 512;
                int cc = j & 511;
                int row = cc >> 2, q = cc & 3;
                const int8_t* src = (plane ? Wql : Wqh) + (size_t)(n0 + row) * D_IN + kc0 + q * 16;
                cp16(bb + (plane ? QWL : QWH) + row * QROW + q * 16, src);
            }
        }
        CP_COMMIT();
    };

    issue(0, 0);

    for (int it = 0; it < QNIT; it++) {
        const int b = it & 1;
        const uint32_t bb = sb + b * QBUF;
        CP_WAIT0();
        __syncthreads();
        if (it + 1 < QNIT) issue(it + 1, b ^ 1);

        #pragma unroll
        for (int kq = 0; kq < 2; kq++) {
            const uint32_t koff = kq * 32 + ((lane >> 4) << 4);
            uint32_t a_h[2][4], a_l[2][4], bh[4][2], bl[4][2];
            #pragma unroll
            for (int mt = 0; mt < 2; mt++) {
                uint32_t off = (uint32_t)(warpM + mt * 16 + (lane & 15)) * QROW + koff;
                ldsm4(a_h[mt], bb + QAH + off);
                ldsm4(a_l[mt], bb + QAL + off);
            }
            #pragma unroll
            for (int nt2 = 0; nt2 < 2; nt2++) {
                uint32_t off = (uint32_t)(warpN + nt2 * 16 + (lane & 15)) * QROW + koff;
                uint32_t r[4];
                ldsm4(r, bb + QWH + off);
                bh[2 * nt2][0] = r[0]; bh[2 * nt2][1] = r[2];
                bh[2 * nt2 + 1][0] = r[1]; bh[2 * nt2 + 1][1] = r[3];
                ldsm4(r, bb + QWL + off);
                bl[2 * nt2][0] = r[0]; bl[2 * nt2][1] = r[2];
                bl[2 * nt2 + 1][0] = r[1]; bl[2 * nt2 + 1][1] = r[3];
            }
            #pragma unroll
            for (int mt = 0; mt < 2; mt++)
                #pragma unroll
                for (int nt = 0; nt < 4; nt++) {
                    mma_s8(hh[mt][nt], a_h[mt], bh[nt]);
                    mma_s8(cr[mt][nt], a_h[mt], bl[nt]);
                    mma_s8(cr[mt][nt], a_l[mt], bh[nt]);
                }
        }
    }

    // epilogue: D = (hh*256 + cr) * 256 * sA[row] * sW[col]; +bias, relu, bf16 split
    #pragma unroll
    for (int mt = 0; mt < 2; mt++) {
        const int r1 = m0 + warpM + mt * 16 + (lane >> 2);
        const float fa1 = 256.f * sA[r1];
        const float fa2 = 256.f * sA[r1 + 8];
        #pragma unroll
        for (int nt = 0; nt < 4; nt++) {
            const int ng = n0 + warpN + nt * 8 + ((lane & 3) << 1);
            float2 sw2 = *(const float2*)(sW + ng);
            float2 bv = *(const float2*)(bias + ng);
            float v00 = fmaf(256.f, (float)hh[mt][nt][0], (float)cr[mt][nt][0]) * fa1 * sw2.x + bv.x;
            float v01 = fmaf(256.f, (float)hh[mt][nt][1], (float)cr[mt][nt][1]) * fa1 * sw2.y + bv.y;
            float v10 = fmaf(256.f, (float)hh[mt][nt][2], (float)cr[mt][nt][2]) * fa2 * sw2.x + bv.x;
            float v11 = fmaf(256.f, (float)hh[mt][nt][3], (float)cr[mt][nt][3]) * fa2 * sw2.y + bv.y;
            v00 = fmaxf(v00, 0.f); v01 = fmaxf(v01, 0.f);
            v10 = fmaxf(v10, 0.f); v11 = fmaxf(v11, 0.f);
            __nv_bfloat16 h00 = __float2bfloat16(v00), h01 = __float2bfloat16(v01);
            __nv_bfloat16 h10 = __float2bfloat16(v10), h11 = __float2bfloat16(v11);
            __nv_bfloat162 hi0 = {h00, h01}, hi1 = {h10, h11};
            __nv_bfloat162 lo0 = __floats2bfloat162_rn(v00 - __bfloat162float(h00),
                                                       v01 - __bfloat162float(h01));
            __nv_bfloat162 lo1 = __floats2bfloat162_rn(v10 - __bfloat162float(h10),
                                                       v11 - __bfloat162float(h11));
            *(__nv_bfloat162*)(Oh + (size_t)r1 * H1 + ng) = hi0;
            *(__nv_bfloat162*)(Ol + (size_t)r1 * H1 + ng) = lo0;
            *(__nv_bfloat162*)(Oh + (size_t)(r1 + 8) * H1 + ng) = hi1;
            *(__nv_bfloat162*)(Ol + (size_t)(r1 + 8) * H1 + ng) = lo1;
        }
    }
}

// ===========================================================================
// Fused tail (unchanged from R6): GEMM2 + 12 layers + final retrieval.
// ===========================================================================
#define LDA 136
#define TAIL_SMEM ((128 * LDA * 2 + 256 * LDA * 2) * 2 + 256 * 4)

__global__ __launch_bounds__(512, 1) void fused_tail(
    const __nv_bfloat16* __restrict__ h1h, const __nv_bfloat16* __restrict__ h1l,
    const __nv_bfloat16* __restrict__ Wh2, const __nv_bfloat16* __restrict__ Wl2,
    const float* __restrict__ b2,
    const __nv_bfloat16* __restrict__ WhC, const __nv_bfloat16* __restrict__ WlC,
    const float* __restrict__ consB,
    const __nv_bfloat16* __restrict__ WfH, const __nv_bfloat16* __restrict__ WfL,
    const float* __restrict__ retB, const float* __restrict__ aw,
    float* __restrict__ out) {
    extern __shared__ __nv_bfloat16 smt[];
    __nv_bfloat16* sAh = smt;
    __nv_bfloat16* sAl = sAh + 128 * LDA;
    __nv_bfloat16* sWh = sAl + 128 * LDA;
    __nv_bfloat16* sWl = sWh + 256 * LDA;
    float* wsum = (float*)(sWl + 256 * LDA);
    float* saw  = wsum + 128;

    const int tid = threadIdx.x;
    const int wid = tid >> 5, lane = tid & 31;
    const int wm = wid & 3;
    const int wn = wid >> 2;
    const int m0 = blockIdx.x * 128;

    const uint32_t aAh = smem_u32(sAh), aAl = smem_u32(sAl);
    const uint32_t aWh = smem_u32(sWh), aWl = smem_u32(sWl);

    auto issueW = [&](const __nv_bfloat16* srcH, const __nv_bfloat16* srcL,
                      int srcStride, int slot) {
        #pragma unroll
        for (int t = 0; t < 8; t++) {
            int idx = tid + t * 512;
            int half = idx >= 2048;
            int cc = idx & 2047;
            int row = cc >> 4, q = cc & 15;
            const __nv_bfloat16* src = (half ? srcL : srcH) + (size_t)row * srcStride + q * 8;
            cp16((half ? aWl : aWh) + (uint32_t)((slot * 128 + row) * LDA + q * 8) * 2, src);
        }
        CP_COMMIT();
    };
    auto issueAct = [&](int kc) {
        #pragma unroll
        for (int t = 0; t < 8; t++) {
            int idx = tid + t * 512;
            int half = idx >= 2048;
            int cc = idx & 2047;
            int row = cc >> 4, q = cc & 15;
            const __nv_bfloat16* src = (half ? h1l : h1h)
                + (size_t)(m0 + row) * H1 + kc * 128 + q * 8;
            cp16((half ? aAl : aAh) + (uint32_t)(row * LDA + q * 8) * 2, src);
        }
        CP_COMMIT();
    };
    auto issueFin = [&](int k) {
        #pragma unroll
        for (int t = 0; t < 16; t++) {
            int idx = tid + t * 512;
            int half = idx >= 4096;
            int cc = idx & 4095;
            int row = cc >> 4, q = cc & 15;
            const __nv_bfloat16* src = (half ? WfL : WfH)
                + (size_t)k * 256 * FEAT + (size_t)row * FEAT + q * 8;
            cp16((half ? aWl : aWh) + (uint32_t)(row * LDA + q * 8) * 2, src);
        }
        CP_COMMIT();
    };

    auto mma128 = [&](float acc4[2][4][4], int slot) {
        const uint32_t base = (uint32_t)(slot * 128 * LDA) * 2;
        #pragma unroll
        for (int ch = 0; ch < 8; ch++) {
            const int colh = ch * 16 + ((lane >> 4) << 3);
            uint32_t a_h[2][4], a_l[2][4], bfr[4][2];
            #pragma unroll
            for (int mt = 0; mt < 2; mt++) {
                int row = wm * 32 + mt * 16 + (lane & 15);
                ldsm4(a_h[mt], aAh + (uint32_t)(row * LDA + colh) * 2);
                ldsm4(a_l[mt], aAl + (uint32_t)(row * LDA + colh) * 2);
            }
            #pragma unroll
            for (int nt2 = 0; nt2 < 2; nt2++) {
                int row = wn * 32 + nt2 * 16 + (lane & 15);
                uint32_t r[4];
                ldsm4(r, aWh + base + (uint32_t)(row * LDA + colh) * 2);
                bfr[2 * nt2][0] = r[0]; bfr[2 * nt2][1] = r[2];
                bfr[2 * nt2 + 1][0] = r[1]; bfr[2 * nt2 + 1][1] = r[3];
            }
            #pragma unroll
            for (int mt = 0; mt < 2; mt++)
                #pragma unroll
                for (int nt = 0; nt < 4; nt++) mma_bf16(acc4[mt][nt], a_h[mt], bfr[nt]);
            #pragma unroll
            for (int mt = 0; mt < 2; mt++)
                #pragma unroll
                for (int nt = 0; nt < 4; nt++) mma_bf16(acc4[mt][nt], a_l[mt], bfr[nt]);
            #pragma unroll
            for (int nt2 = 0; nt2 < 2; nt2++) {
                int row = wn * 32 + nt2 * 16 + (lane & 15);
                uint32_t r[4];
                ldsm4(r, aWl + base + (uint32_t)(row * LDA + colh) * 2);
                bfr[2 * nt2][0] = r[0]; bfr[2 * nt2][1] = r[2];
                bfr[2 * nt2 + 1][0] = r[1]; bfr[2 * nt2 + 1][1] = r[3];
            }
            #pragma unroll
            for (int mt = 0; mt < 2; mt++)
                #pragma unroll
                for (int nt = 0; nt < 4; nt++) mma_bf16(acc4[mt][nt], a_h[mt], bfr[nt]);
        }
    };
    auto epilogue = [&](float acc4[2][4][4], const float* biasp) {
        #pragma unroll
        for (int mt = 0; mt < 2; mt++) {
            const int row = wm * 32 + mt * 16 + (lane >> 2);
            #pragma unroll
            for (int nt = 0; nt < 4; nt++) {
                const int col = wn * 32 + nt * 8 + ((lane & 3) << 1);
                float2 bv = *(const float2*)(biasp + col);
                float v00 = fmaxf(acc4[mt][nt][0] + bv.x, 0.f);
                float v01 = fmaxf(acc4[mt][nt][1] + bv.y, 0.f);
                float v10 = fmaxf(acc4[mt][nt][2] + bv.x, 0.f);
                float v11 = fmaxf(acc4[mt][nt][3] + bv.y, 0.f);
                __nv_bfloat16 h00 = __float2bfloat16(v00), h01 = __float2bfloat16(v01);
                __nv_bfloat16 h10 = __float2bfloat16(v10), h11 = __float2bfloat16(v11);
                __nv_bfloat162 hi0 = {h00, h01}, hi1 = {h10, h11};
                __nv_bfloat162 lo0 = __floats2bfloat162_rn(v00 - __bfloat162float(h00),
                                                           v01 - __bfloat162float(h01));
                __nv_bfloat162 lo1 = __floats2bfloat162_rn(v10 - __bfloat162float(h10),
                                                           v11 - __bfloat162float(h11));
                *(__nv_bfloat162*)(sAh + row * LDA + col) = hi0;
                *(__nv_bfloat162*)(sAl + row * LDA + col) = lo0;
                *(__nv_bfloat162*)(sAh + (row + 8) * LDA + col) = hi1;
                *(__nv_bfloat162*)(sAl + (row + 8) * LDA + col) = lo1;
            }
        }
    };

    if (tid < 128) saw[tid] = aw[m0 + tid];

    issueW(Wh2, Wl2, H1, 0);
    issueAct(0);
    {
        #pragma unroll
        for (int t = 0; t < 8; t++) {
            int idx = tid + t * 512;
            int half = idx >= 2048;
            int cc = idx & 2047;
            int row = cc >> 4, q = cc & 15;
            const __nv_bfloat16* src = (half ? Wl2 : Wh2) + (size_t)row * H1 + 128 + q * 8;
            cp16((half ? aWl : aWh) + (uint32_t)((128 + row) * LDA + q * 8) * 2, src);
        }
        CP_COMMIT();
    }

    float acc4[2][4][4];
    #pragma unroll
    for (int i = 0; i < 2; i++)
        #pragma unroll
        for (int j = 0; j < 4; j++)
            #pragma unroll
            for (int q = 0; q < 4; q++) acc4[i][j][q] = 0.f;

    CP_WAIT1();
    __syncthreads();
    mma128(acc4, 0);
    __syncthreads();
    issueAct(1);
    issueW(WhC, WlC, FEAT, 0);
    CP_WAIT1();
    __syncthreads();
    mma128(acc4, 1);
    __syncthreads();
    epilogue(acc4, b2);
    __syncthreads();

    for (int l = 0; l < DEPTH; l++) {
        if (l + 1 < DEPTH)
            issueW(WhC + (size_t)(l + 1) * FEAT * FEAT,
                   WlC + (size_t)(l + 1) * FEAT * FEAT, FEAT, (l + 1) & 1);
        if (l + 1 < DEPTH) { CP_WAIT1(); } else { CP_WAIT0(); }
        __syncthreads();
        #pragma unroll
        for (int i = 0; i < 2; i++)
            #pragma unroll
            for (int j = 0; j < 4; j++)
                #pragma unroll
                for (int q = 0; q < 4; q++) acc4[i][j][q] = 0.f;
        mma128(acc4, l & 1);
        __syncthreads();
        epilogue(acc4, consB + (size_t)l * FEAT);
        __syncthreads();
    }

    issueFin(0);
    CP_WAIT0();
    const float cfac = 0.42f * 1.8f / (float)CAP;
    for (int k = 0; k < NCOND; k++) {
        __syncthreads();
        if (tid < 128) wsum[tid] = 0.f;

        float acc8[2][8][4];
        #pragma unroll
        for (int i = 0; i < 2; i++)
            #pragma unroll
            for (int j = 0; j < 8; j++)
                #pragma unroll
                for (int q = 0; q < 4; q++) acc8[i][j][q] = 0.f;

        #pragma unroll
        for (int ch = 0; ch < 8; ch++) {
            const int colh = ch * 16 + ((lane >> 4) << 3);
            uint32_t a_h[2][4], a_l[2][4], bfr[8][2];
            #pragma unroll
            for (int mt = 0; mt < 2; mt++) {
                int row = wm * 32 + mt * 16 + (lane & 15);
                ldsm4(a_h[mt], aAh + (uint32_t)(row * LDA + colh) * 2);
                ldsm4(a_l[mt], aAl + (uint32_t)(row * LDA + colh) * 2);
            }
            #pragma unroll
            for (int nt2 = 0; nt2 < 4; nt2++) {
                int row = wn * 64 + nt2 * 16 + (lane & 15);
                uint32_t r[4];
                ldsm4(r, aWh + (uint32_t)(row * LDA + colh) * 2);
                bfr[2 * nt2][0] = r[0]; bfr[2 * nt2][1] = r[2];
                bfr[2 * nt2 + 1][0] = r[1]; bfr[2 * nt2 + 1][1] = r[3];
            }
            #pragma unroll
            for (int mt = 0; mt < 2; mt++)
                #pragma unroll
                for (int nt = 0; nt < 8; nt++) mma_bf16(acc8[mt][nt], a_h[mt], bfr[nt]);
            #pragma unroll
            for (int mt = 0; mt < 2; mt++)
                #pragma unroll
                for (int nt = 0; nt < 8; nt++) mma_bf16(acc8[mt][nt], a_l[mt], bfr[nt]);
            #pragma unroll
            for (int nt2 = 0; nt2 < 4; nt2++) {
                int row = wn * 64 + nt2 * 16 + (lane & 15);
                uint32_t r[4];
                ldsm4(r, aWl + (uint32_t)(row * LDA + colh) * 2);
                bfr[2 * nt2][0] = r[0]; bfr[2 * nt2][1] = r[2];
                bfr[2 * nt2 + 1][0] = r[1]; bfr[2 * nt2 + 1][1] = r[3];
            }
            #pragma unroll
            for (int mt = 0; mt < 2; mt++)
                #pragma unroll
                for (int nt = 0; nt < 8; nt++) mma_bf16(acc8[mt][nt], a_h[mt], bfr[nt]);
        }
        __syncthreads();
        if (k + 1 < NCOND) issueFin(k + 1);

        if (wn >= 2) {
            #pragma unroll
            for (int mt = 0; mt < 2; mt++) {
                const int r1 = wm * 32 + mt * 16 + (lane >> 2);
                float p1 = 0.f, p2 = 0.f;
                #pragma unroll
                for (int nt = 0; nt < 8; nt++) {
                    const int e0 = (wn - 2) * 64 + nt * 8 + ((lane & 3) << 1);
                    float m00 = __bfloat162float(sAh[r1 * LDA + e0]) +
                                __bfloat162float(sAl[r1 * LDA + e0]);
                    float m01 = __bfloat162float(sAh[r1 * LDA + e0 + 1]) +
                                __bfloat162float(sAl[r1 * LDA + e0 + 1]);
                    float m10 = __bfloat162float(sAh[(r1 + 8) * LDA + e0]) +
                                __bfloat162float(sAl[(r1 + 8) * LDA + e0]);
                    float m11 = __bfloat162float(sAh[(r1 + 8) * LDA + e0 + 1]) +
                                __bfloat162float(sAl[(r1 + 8) * LDA + e0 + 1]);
                    p1 += acc8[mt][nt][0] * m00 + acc8[mt][nt][1] * m01;
                    p2 += acc8[mt][nt][2] * m10 + acc8[mt][nt][3] * m11;
                }
                atomicAdd(&wsum[r1], p1);
                atomicAdd(&wsum[r1 + 8], p2);
            }
        }
        __syncthreads();
        if (tid < 128) wsum[tid] = wsum[tid] * cfac + 0.3f * saw[tid];
        __syncthreads();

        if (wn < 2) {
            #pragma unroll
            for (int mt = 0; mt < 2; mt++) {
                const int rl = wm * 32 + mt * 16 + (lane >> 2);
                const float w1 = wsum[rl], w2 = wsum[rl + 8];
                #pragma unroll
                for (int nt = 0; nt < 8; nt++) {
                    const int col = wn * 64 + nt * 8 + ((lane & 3) << 1);
                    float2 bv = *(const float2*)(retB + (size_t)k * FEAT + col);
                    size_t base1 = (size_t)(m0 + rl) * (NCOND * FEAT) + (size_t)k * FEAT + col;
                    size_t base2 = (size_t)(m0 + rl + 8) * (NCOND * FEAT) + (size_t)k * FEAT + col;
                    *(float2*)(out + base1) = make_float2((acc8[mt][nt][0] + bv.x) * w1,
                                                          (acc8[mt][nt][1] + bv.y) * w1);
                    *(float2*)(out + base2) = make_float2((acc8[mt][nt][2] + bv.x) * w2,
                                                          (acc8[mt][nt][3] + bv.y) * w2);
                }
            }
        }
        if (k + 1 < NCOND) CP_WAIT0();
    }
}

// ===========================================================================
extern "C" void kernel_launch(void* const* d_in, const int* in_sizes, int n_in,
                              void* d_out, int out_size) {
    const float* sup  = (const float*)d_in[0];
    const float* anom = (const float*)d_in[1];
    const float* ind  = (const float*)d_in[2];
    const float* ipW1 = (const float*)d_in[3];
    const float* ipb1 = (const float*)d_in[4];
    const float* ipW2 = (const float*)d_in[5];
    const float* ipb2 = (const float*)d_in[6];
    const float* consW = (const float*)d_in[7];
    const float* consB = (const float*)d_in[8];
    const float* refp = (const float*)d_in[9];
    const float* objp = (const float*)d_in[10];
    const float* retW = (const float*)d_in[11];
    const float* retB = (const float*)d_in[12];
    float* out = (float*)d_out;

    int8_t *Aqh, *Aql, *Wqh, *Wql;
    __nv_bfloat16 *Wh2, *Wl2, *WhC, *WlC, *h1h, *h1l, *WfH, *WfL;
    float *aw, *sA, *sW;
    cudaGetSymbolAddress((void**)&Aqh, g_Aqh);
    cudaGetSymbolAddress((void**)&Aql, g_Aql);
    cudaGetSymbolAddress((void**)&Wqh, g_Wqh);
    cudaGetSymbolAddress((void**)&Wql, g_Wql);
    cudaGetSymbolAddress((void**)&sA, g_sA);
    cudaGetSymbolAddress((void**)&sW, g_sW);
    cudaGetSymbolAddress((void**)&Wh2, g_Wh2);
    cudaGetSymbolAddress((void**)&Wl2, g_Wl2);
    cudaGetSymbolAddress((void**)&WhC, g_WhC);
    cudaGetSymbolAddress((void**)&WlC, g_WlC);
    cudaGetSymbolAddress((void**)&h1h, g_h1h);
    cudaGetSymbolAddress((void**)&h1l, g_h1l);
    cudaGetSymbolAddress((void**)&WfH, g_WfinH);
    cudaGetSymbolAddress((void**)&WfL, g_WfinL);
    cudaGetSymbolAddress((void**)&aw, g_aw);

    cudaFuncSetAttribute(gemm1_q, cudaFuncAttributeMaxDynamicSharedMemorySize, QSMEM);
    cudaFuncSetAttribute(fused_tail, cudaFuncAttributeMaxDynamicSharedMemorySize, TAIL_SMEM);

    // launch order chosen so gemm1_q is the 6th launch (ncu -s 5 -c 1 capture)
    quantW_kernel<<<H1, 128>>>(ipW1, Wqh, Wql, sW);                                   // 1
    quantA_kernel<<<BB, 128>>>(sup, anom, ind, Aqh, Aql, sA);                         // 2
    aw_kernel<<<BB * 32 / 256, 256>>>(anom, aw);                                      // 3
    mkfin_kernel<<<NCOND, 256>>>(refp, objp, WfH, WfL);                               // 4
    tsplit_kernel<<<dim3(H1 / 32, FEAT / 32, 1), dim3(32, 8)>>>(ipW2, Wh2, Wl2, H1, FEAT, FEAT * H1); // 5
    gemm1_q<<<dim3(2, BB / 128), 512, QSMEM>>>(Aqh, Aql, Wqh, Wql, sA, sW, ipb1, h1h, h1l);           // 6 (profiled)
    tsplit_kernel<<<dim3(FEAT / 32, FEAT / 32, DEPTH), dim3(32, 8)>>>(consW, WhC, WlC, FEAT, FEAT, FEAT * FEAT); // 7
    tsplit_kernel<<<dim3(FEAT / 32, FEAT / 32, NCOND), dim3(32, 8)>>>(retW, WfH, WfL, FEAT, FEAT, 256 * FEAT);   // 8
    fused_tail<<<BB / 128, 512, TAIL_SMEM>>>(
        h1h, h1l, Wh2, Wl2, ipb2, WhC, WlC, consB, WfH, WfL, retB, aw, out);          // 9
}

// round 11
// speedup vs baseline: 1.6292x; 1.6261x over previous
#include <cuda_runtime.h>
#include <cuda_bf16.h>
#include <stdint.h>

#define BB 16384
#define D_SUP 1024
#define D_ANOM 128
#define D_IND 2048
#define D_IN 3200
#define H1 256
#define FEAT 128
#define DEPTH 12
#define NCOND 14
#define CAP 256

// ---------------- scratch (device globals; no allocation allowed) ----------
__device__ __nv_bfloat16 g_Wh1[H1 * D_IN];           // W1^T hi [256][3200]
__device__ __nv_bfloat16 g_Wl1[H1 * D_IN];
__device__ __nv_bfloat16 g_Wh2[FEAT * H1];           // W2^T hi [128][256]
__device__ __nv_bfloat16 g_Wl2[FEAT * H1];
__device__ __nv_bfloat16 g_WhC[DEPTH * FEAT * FEAT]; // consW^T hi [12][128][128]
__device__ __nv_bfloat16 g_WlC[DEPTH * FEAT * FEAT];
__device__ __nv_bfloat16 g_h1h[BB * H1];             // h1 hi/lo [16384][256]
__device__ __nv_bfloat16 g_h1l[BB * H1];
__device__ __nv_bfloat16 g_WfinH[NCOND * 256 * FEAT]; // [k][256][128]: rows 0-127 retW^T, 128-255 Mk^T
__device__ __nv_bfloat16 g_WfinL[NCOND * 256 * FEAT];
__device__ float g_aw[BB];

// ---------------- helpers --------------------------------------------------
__device__ __forceinline__ uint32_t smem_u32(const void* p) {
    uint32_t a;
    asm("{ .reg .u64 t; cvta.to.shared.u64 t, %1; cvt.u32.u64 %0, t; }" : "=r"(a) : "l"(p));
    return a;
}
__device__ __forceinline__ void ldsm4(uint32_t* r, uint32_t addr) {
    asm volatile("ldmatrix.sync.aligned.m8n8.x4.shared.b16 {%0,%1,%2,%3}, [%4];"
                 : "=r"(r[0]), "=r"(r[1]), "=r"(r[2]), "=r"(r[3]) : "r"(addr));
}
__device__ __forceinline__ void mma_bf16(float* c, const uint32_t* a, const uint32_t* b) {
    asm volatile("mma.sync.aligned.m16n8k16.row.col.f32.bf16.bf16.f32 "
                 "{%0,%1,%2,%3}, {%4,%5,%6,%7}, {%8,%9}, {%0,%1,%2,%3};"
                 : "+f"(c[0]), "+f"(c[1]), "+f"(c[2]), "+f"(c[3])
                 : "r"(a[0]), "r"(a[1]), "r"(a[2]), "r"(a[3]), "r"(b[0]), "r"(b[1]));
}
__device__ __forceinline__ void cp16(uint32_t smem, const void* g) {
    asm volatile("cp.async.cg.shared.global [%0], [%1], 16;" :: "r"(smem), "l"(g));
}
#define CP_COMMIT() asm volatile("cp.async.commit_group;" ::: "memory")
#define CP_WAIT0()  asm volatile("cp.async.wait_group 0;" ::: "memory")
#define CP_WAIT1()  asm volatile("cp.async.wait_group 1;" ::: "memory")

// ---------------- aw[b] = mean(|anomaly[b,:]|) -----------------------------
__global__ __launch_bounds__(256) void aw_kernel(const float* __restrict__ anom,
                                                 float* __restrict__ aw) {
    int warp = (blockIdx.x * blockDim.x + threadIdx.x) >> 5;
    int lane = threadIdx.x & 31;
    if (warp >= BB) return;
    float4 v = *(const float4*)(anom + (size_t)warp * D_ANOM + lane * 4);
    float s = fabsf(v.x) + fabsf(v.y) + fabsf(v.z) + fabsf(v.w);
    #pragma unroll
    for (int o = 16; o; o >>= 1) s += __shfl_xor_sync(0xFFFFFFFFu, s, o);
    if (lane == 0) aw[warp] = s * (1.0f / D_ANOM);
}

// ---------------- Mk^T hi/lo into Wfin rows 128-255 ------------------------
__global__ __launch_bounds__(256) void mkfin_kernel(const float* __restrict__ refp,
                                                    const float* __restrict__ objp,
                                                    __nv_bfloat16* __restrict__ WfH,
                                                    __nv_bfloat16* __restrict__ WfL) {
    const int k = blockIdx.x;
    __shared__ float Rs[32][FEAT];
    __shared__ float Os[32][FEAT];
    const int tid = threadIdx.x;
    const int tc = tid & 15;
    const int tr = tid >> 4;
    float acc[8][8] = {};
    const float* rb = refp + (size_t)k * CAP * FEAT;
    const float* ob = objp + (size_t)k * CAP * FEAT;
    for (int c0 = 0; c0 < CAP; c0 += 32) {
        #pragma unroll
        for (int i = tid; i < 32 * FEAT / 4; i += 256) {
            int c = i >> 5, d4 = (i & 31) * 4;
            *(float4*)&Rs[c][d4] = *(const float4*)(rb + (size_t)(c0 + c) * FEAT + d4);
            *(float4*)&Os[c][d4] = *(const float4*)(ob + (size_t)(c0 + c) * FEAT + d4);
        }
        __syncthreads();
        #pragma unroll 8
        for (int c = 0; c < 32; c++) {
            float a[8], b[8];
            #pragma unroll
            for (int i = 0; i < 8; i += 4) *(float4*)&a[i] = *(const float4*)&Rs[c][tr * 8 + i];
            #pragma unroll
            for (int j = 0; j < 8; j += 4) *(float4*)&b[j] = *(const float4*)&Os[c][tc * 8 + j];
            #pragma unroll
            for (int i = 0; i < 8; i++)
                #pragma unroll
                for (int j = 0; j < 8; j++) acc[i][j] += a[i] * b[j];
        }
        __syncthreads();
    }
    #pragma unroll
    for (int j = 0; j < 8; j++) {
        int e = tc * 8 + j;
        __nv_bfloat16 hv[8], lv[8];
        #pragma unroll
        for (int i = 0; i < 8; i++) {
            float v = acc[i][j];
            __nv_bfloat16 hi = __float2bfloat16(v);
            hv[i] = hi;
            lv[i] = __float2bfloat16(v - __bfloat162float(hi));
        }
        size_t base = (size_t)k * 256 * FEAT + (size_t)(128 + e) * FEAT + tr * 8;
        *(uint4*)(WfH + base) = *(uint4*)hv;
        *(uint4*)(WfL + base) = *(uint4*)lv;
    }
}

// ---------------- transpose + hi/lo split:  dst[n][k] = W[k][n] ------------
__global__ __launch_bounds__(256) void tsplit_kernel(const float* __restrict__ W,
                                                     __nv_bfloat16* __restrict__ Wh,
                                                     __nv_bfloat16* __restrict__ Wl,
                                                     int K, int N, int dstBatchStride) {
    const int batch = blockIdx.z;
    W += (size_t)batch * K * N;
    Wh += (size_t)batch * dstBatchStride;
    Wl += (size_t)batch * dstBatchStride;
    __shared__ float t[32][33];
    const int k0 = blockIdx.x * 32;
    const int n0 = blockIdx.y * 32;
    const int tx = threadIdx.x, ty = threadIdx.y;
    #pragma unroll
    for (int i = 0; i < 4; i++)
        t[ty + 8 * i][tx] = W[(size_t)(k0 + ty + 8 * i) * N + n0 + tx];
    __syncthreads();
    #pragma unroll
    for (int i = 0; i < 4; i++) {
        int n = n0 + ty + 8 * i;
        int k = k0 + tx;
        float v = t[tx][ty + 8 * i];
        __nv_bfloat16 hi = __float2bfloat16(v);
        __nv_bfloat16 lo = __float2bfloat16(v - __bfloat162float(hi));
        Wh[(size_t)n * K + k] = hi;
        Wl[(size_t)n * K + k] = lo;
    }
}

// ===========================================================================
// GEMM1 v3: BM=64, BN=128, 256 threads, 40KB/buffer -> 2 CTAs/SM.
//   h1 = relu(concat(sup,anom,ind) @ W1 + b1) -> bf16 hi/lo
// ===========================================================================
#define G3_BUF 39936
#define G3_OF  0
#define G3_OAH 9216
#define G3_OAL 14336
#define G3_OWH 19456
#define G3_OWL 29696
#define G3_SMEM (2 * G3_BUF)
#define G3_NIT (D_IN / 32)

__global__ __launch_bounds__(256, 2) void gemm1_v3(
    const float* __restrict__ A0, const float* __restrict__ A1,
    const float* __restrict__ A2,
    const __nv_bfloat16* __restrict__ Bh, const __nv_bfloat16* __restrict__ Bl,
    const float* __restrict__ bias,
    __nv_bfloat16* __restrict__ Oh, __nv_bfloat16* __restrict__ Ol) {
    extern __shared__ char sm[];
    const uint32_t sb = smem_u32(sm);
    const int tid = threadIdx.x;
    const int wid = tid >> 5, lane = tid & 31;
    const int warpM = (wid & 1) * 32;
    const int warpN = (wid >> 1) * 32;
    const int n0 = blockIdx.x * 128;
    const int m0 = blockIdx.y * 64;

    float acc[2][4][4];
    #pragma unroll
    for (int i = 0; i < 2; i++)
        #pragma unroll
        for (int j = 0; j < 4; j++)
            #pragma unroll
            for (int q = 0; q < 4; q++) acc[i][j][q] = 0.f;

    auto issue = [&](int it, int b) {
        const int k0 = it * 32;
        const float* Ap; int lda, kk;
        if (k0 < D_SUP)               { Ap = A0; lda = D_SUP;  kk = k0; }
        else if (k0 < D_SUP + D_ANOM) { Ap = A1; lda = D_ANOM; kk = k0 - D_SUP; }
        else                          { Ap = A2; lda = D_IND;  kk = k0 - D_SUP - D_ANOM; }
        const uint32_t bb = sb + b * G3_BUF;
        #pragma unroll
        for (int t = 0; t < 2; t++) {
            int idx = tid + t * 256;          // 512 float4 chunks of A
            int row = idx >> 3, q = idx & 7;
            cp16(bb + G3_OF + row * 144 + q * 16,
                 Ap + (size_t)(m0 + row) * lda + kk + q * 4);
        }
        #pragma unroll
        for (int t = 0; t < 4; t++) {
            int idx = tid + t * 256;          // 1024 chunks of W (hi then lo)
            int plane = idx >= 512;
            int cc = idx & 511;
            int row = cc >> 2, q = cc & 3;
            cp16(bb + (plane ? G3_OWL : G3_OWH) + row * 80 + q * 16,
                 (plane ? Bl : Bh) + (size_t)(n0 + row) * D_IN + k0 + q * 8);
        }
        CP_COMMIT();
    };

    issue(0, 0);

    for (int it = 0; it < G3_NIT; it++) {
        const int b = it & 1;
        const uint32_t bb = sb + b * G3_BUF;
        CP_WAIT0();
        __syncthreads();
        if (it + 1 < G3_NIT) issue(it + 1, b ^ 1);

        // convert fp32 stage -> bf16 hi/lo
        #pragma unroll
        for (int t = 0; t < 2; t++) {
            int idx = tid + t * 256;
            int row = idx >> 3, q = idx & 7;
            float4 v = *(const float4*)(sm + (size_t)b * G3_BUF + G3_OF + row * 144 + q * 16);
            __nv_bfloat16 hx = __float2bfloat16(v.x), hy = __float2bfloat16(v.y);
            __nv_bfloat16 hz = __float2bfloat16(v.z), hw = __float2bfloat16(v.w);
            __nv_bfloat162 h01 = {hx, hy}, h23 = {hz, hw};
            __nv_bfloat162 l01 = __floats2bfloat162_rn(v.x - __bfloat162float(hx),
                                                       v.y - __bfloat162float(hy));
            __nv_bfloat162 l23 = __floats2bfloat162_rn(v.z - __bfloat162float(hz),
                                                       v.w - __bfloat162float(hw));
            size_t off = (size_t)b * G3_BUF + row * 80 + q * 8;
            *(__nv_bfloat162*)(sm + off + G3_OAH) = h01;
            *(__nv_bfloat162*)(sm + off + G3_OAH + 4) = h23;
            *(__nv_bfloat162*)(sm + off + G3_OAL) = l01;
            *(__nv_bfloat162*)(sm + off + G3_OAL + 4) = l23;
        }
        __syncthreads();

        #pragma unroll
        for (int kq = 0; kq < 2; kq++) {
            const uint32_t colb = (uint32_t)(kq * 16 + ((lane >> 4) << 3)) * 2;
            uint32_t a_h[2][4], a_l[2][4], bfr[4][2];
            #pragma unroll
            for (int mt = 0; mt < 2; mt++) {
                uint32_t off = (uint32_t)(warpM + mt * 16 + (lane & 15)) * 80 + colb;
                ldsm4(a_h[mt], bb + G3_OAH + off);
                ldsm4(a_l[mt], bb + G3_OAL + off);
            }
            #pragma unroll
            for (int nt2 = 0; nt2 < 2; nt2++) {
                uint32_t off = (uint32_t)(warpN + nt2 * 16 + (lane & 15)) * 80 + colb;
                uint32_t r[4];
                ldsm4(r, bb + G3_OWH + off);
                bfr[2 * nt2][0] = r[0]; bfr[2 * nt2][1] = r[2];
                bfr[2 * nt2 + 1][0] = r[1]; bfr[2 * nt2 + 1][1] = r[3];
            }
            #pragma unroll
            for (int mt = 0; mt < 2; mt++)
                #pragma unroll
                for (int nt = 0; nt < 4; nt++) mma_bf16(acc[mt][nt], a_h[mt], bfr[nt]);
            #pragma unroll
            for (int mt = 0; mt < 2; mt++)
                #pragma unroll
                for (int nt = 0; nt < 4; nt++) mma_bf16(acc[mt][nt], a_l[mt], bfr[nt]);
            #pragma unroll
            for (int nt2 = 0; nt2 < 2; nt2++) {
                uint32_t off = (uint32_t)(warpN + nt2 * 16 + (lane & 15)) * 80 + colb;
                uint32_t r[4];
                ldsm4(r, bb + G3_OWL + off);
                bfr[2 * nt2][0] = r[0]; bfr[2 * nt2][1] = r[2];
                bfr[2 * nt2 + 1][0] = r[1]; bfr[2 * nt2 + 1][1] = r[3];
            }
            #pragma unroll
            for (int mt = 0; mt < 2; mt++)
                #pragma unroll
                for (int nt = 0; nt < 4; nt++) mma_bf16(acc[mt][nt], a_h[mt], bfr[nt]);
        }
    }

    // epilogue: bias + relu -> bf16 hi/lo
    #pragma unroll
    for (int mt = 0; mt < 2; mt++) {
        const int r0 = m0 + warpM + mt * 16 + (lane >> 2);
        #pragma unroll
        for (int nt = 0; nt < 4; nt++) {
            const int ng = n0 + warpN + nt * 8 + ((lane & 3) << 1);
            float2 bv = *(const float2*)(bias + ng);
            float v00 = fmaxf(acc[mt][nt][0] + bv.x, 0.f);
            float v01 = fmaxf(acc[mt][nt][1] + bv.y, 0.f);
            float v10 = fmaxf(acc[mt][nt][2] + bv.x, 0.f);
            float v11 = fmaxf(acc[mt][nt][3] + bv.y, 0.f);
            __nv_bfloat16 h00 = __float2bfloat16(v00), h01 = __float2bfloat16(v01);
            __nv_bfloat16 h10 = __float2bfloat16(v10), h11 = __float2bfloat16(v11);
            __nv_bfloat162 hi0 = {h00, h01}, hi1 = {h10, h11};
            __nv_bfloat162 lo0 = __floats2bfloat162_rn(v00 - __bfloat162float(h00),
                                                       v01 - __bfloat162float(h01));
            __nv_bfloat162 lo1 = __floats2bfloat162_rn(v10 - __bfloat162float(h10),
                                                       v11 - __bfloat162float(h11));
            *(__nv_bfloat162*)(Oh + (size_t)r0 * H1 + ng) = hi0;
            *(__nv_bfloat162*)(Ol + (size_t)r0 * H1 + ng) = lo0;
            *(__nv_bfloat162*)(Oh + (size_t)(r0 + 8) * H1 + ng) = hi1;
            *(__nv_bfloat162*)(Ol + (size_t)(r0 + 8) * H1 + ng) = lo1;
        }
    }
}

// ===========================================================================
// Fused tail (unchanged): GEMM2 + 12 layers + final retrieval.
// ===========================================================================
#define LDA 136
#define TAIL_SMEM ((128 * LDA * 2 + 256 * LDA * 2) * 2 + 256 * 4)

__global__ __launch_bounds__(512, 1) void fused_tail(
    const __nv_bfloat16* __restrict__ h1h, const __nv_bfloat16* __restrict__ h1l,
    const __nv_bfloat16* __restrict__ Wh2, const __nv_bfloat16* __restrict__ Wl2,
    const float* __restrict__ b2,
    const __nv_bfloat16* __restrict__ WhC, const __nv_bfloat16* __restrict__ WlC,
    const float* __restrict__ consB,
    const __nv_bfloat16* __restrict__ WfH, const __nv_bfloat16* __restrict__ WfL,
    const float* __restrict__ retB, const float* __restrict__ aw,
    float* __restrict__ out) {
    extern __shared__ __nv_bfloat16 smt[];
    __nv_bfloat16* sAh = smt;
    __nv_bfloat16* sAl = sAh + 128 * LDA;
    __nv_bfloat16* sWh = sAl + 128 * LDA;
    __nv_bfloat16* sWl = sWh + 256 * LDA;
    float* wsum = (float*)(sWl + 256 * LDA);
    float* saw  = wsum + 128;

    const int tid = threadIdx.x;
    const int wid = tid >> 5, lane = tid & 31;
    const int wm = wid & 3;
    const int wn = wid >> 2;
    const int m0 = blockIdx.x * 128;

    const uint32_t aAh = smem_u32(sAh), aAl = smem_u32(sAl);
    const uint32_t aWh = smem_u32(sWh), aWl = smem_u32(sWl);

    auto issueW = [&](const __nv_bfloat16* srcH, const __nv_bfloat16* srcL,
                      int srcStride, int slot) {
        #pragma unroll
        for (int t = 0; t < 8; t++) {
            int idx = tid + t * 512;
            int half = idx >= 2048;
            int cc = idx & 2047;
            int row = cc >> 4, q = cc & 15;
            const __nv_bfloat16* src = (half ? srcL : srcH) + (size_t)row * srcStride + q * 8;
            cp16((half ? aWl : aWh) + (uint32_t)((slot * 128 + row) * LDA + q * 8) * 2, src);
        }
        CP_COMMIT();
    };
    auto issueAct = [&](int kc) {
        #pragma unroll
        for (int t = 0; t < 8; t++) {
            int idx = tid + t * 512;
            int half = idx >= 2048;
            int cc = idx & 2047;
            int row = cc >> 4, q = cc & 15;
            const __nv_bfloat16* src = (half ? h1l : h1h)
                + (size_t)(m0 + row) * H1 + kc * 128 + q * 8;
            cp16((half ? aAl : aAh) + (uint32_t)(row * LDA + q * 8) * 2, src);
        }
        CP_COMMIT();
    };
    auto issueFin = [&](int k) {
        #pragma unroll
        for (int t = 0; t < 16; t++) {
            int idx = tid + t * 512;
            int half = idx >= 4096;
            int cc = idx & 4095;
            int row = cc >> 4, q = cc & 15;
            const __nv_bfloat16* src = (half ? WfL : WfH)
                + (size_t)k * 256 * FEAT + (size_t)row * FEAT + q * 8;
            cp16((half ? aWl : aWh) + (uint32_t)(row * LDA + q * 8) * 2, src);
        }
        CP_COMMIT();
    };

    auto mma128 = [&](float acc4[2][4][4], int slot) {
        const uint32_t base = (uint32_t)(slot * 128 * LDA) * 2;
        #pragma unroll
        for (int ch = 0; ch < 8; ch++) {
            const int colh = ch * 16 + ((lane >> 4) << 3);
            uint32_t a_h[2][4], a_l[2][4], bfr[4][2];
            #pragma unroll
            for (int mt = 0; mt < 2; mt++) {
                int row = wm * 32 + mt * 16 + (lane & 15);
                ldsm4(a_h[mt], aAh + (uint32_t)(row * LDA + colh) * 2);
                ldsm4(a_l[mt], aAl + (uint32_t)(row * LDA + colh) * 2);
            }
            #pragma unroll
            for (int nt2 = 0; nt2 < 2; nt2++) {
                int row = wn * 32 + nt2 * 16 + (lane & 15);
                uint32_t r[4];
                ldsm4(r, aWh + base + (uint32_t)(row * LDA + colh) * 2);
                bfr[2 * nt2][0] = r[0]; bfr[2 * nt2][1] = r[2];
                bfr[2 * nt2 + 1][0] = r[1]; bfr[2 * nt2 + 1][1] = r[3];
            }
            #pragma unroll
            for (int mt = 0; mt < 2; mt++)
                #pragma unroll
                for (int nt = 0; nt < 4; nt++) mma_bf16(acc4[mt][nt], a_h[mt], bfr[nt]);
            #pragma unroll
            for (int mt = 0; mt < 2; mt++)
                #pragma unroll
                for (int nt = 0; nt < 4; nt++) mma_bf16(acc4[mt][nt], a_l[mt], bfr[nt]);
            #pragma unroll
            for (int nt2 = 0; nt2 < 2; nt2++) {
                int row = wn * 32 + nt2 * 16 + (lane & 15);
                uint32_t r[4];
                ldsm4(r, aWl + base + (uint32_t)(row * LDA + colh) * 2);
                bfr[2 * nt2][0] = r[0]; bfr[2 * nt2][1] = r[2];
                bfr[2 * nt2 + 1][0] = r[1]; bfr[2 * nt2 + 1][1] = r[3];
            }
            #pragma unroll
            for (int mt = 0; mt < 2; mt++)
                #pragma unroll
                for (int nt = 0; nt < 4; nt++) mma_bf16(acc4[mt][nt], a_h[mt], bfr[nt]);
        }
    };
    auto epilogue = [&](float acc4[2][4][4], const float* biasp) {
        #pragma unroll
        for (int mt = 0; mt < 2; mt++) {
            const int row = wm * 32 + mt * 16 + (lane >> 2);
            #pragma unroll
            for (int nt = 0; nt < 4; nt++) {
                const int col = wn * 32 + nt * 8 + ((lane & 3) << 1);
                float2 bv = *(const float2*)(biasp + col);
                float v00 = fmaxf(acc4[mt][nt][0] + bv.x, 0.f);
                float v01 = fmaxf(acc4[mt][nt][1] + bv.y, 0.f);
                float v10 = fmaxf(acc4[mt][nt][2] + bv.x, 0.f);
                float v11 = fmaxf(acc4[mt][nt][3] + bv.y, 0.f);
                __nv_bfloat16 h00 = __float2bfloat16(v00), h01 = __float2bfloat16(v01);
                __nv_bfloat16 h10 = __float2bfloat16(v10), h11 = __float2bfloat16(v11);
                __nv_bfloat162 hi0 = {h00, h01}, hi1 = {h10, h11};
                __nv_bfloat162 lo0 = __floats2bfloat162_rn(v00 - __bfloat162float(h00),
                                                           v01 - __bfloat162float(h01));
                __nv_bfloat162 lo1 = __floats2bfloat162_rn(v10 - __bfloat162float(h10),
                                                           v11 - __bfloat162float(h11));
                *(__nv_bfloat162*)(sAh + row * LDA + col) = hi0;
                *(__nv_bfloat162*)(sAl + row * LDA + col) = lo0;
                *(__nv_bfloat162*)(sAh + (row + 8) * LDA + col) = hi1;
                *(__nv_bfloat162*)(sAl + (row + 8) * LDA + col) = lo1;
            }
        }
    };

    if (tid < 128) saw[tid] = aw[m0 + tid];

    issueW(Wh2, Wl2, H1, 0);
    issueAct(0);
    {
        #pragma unroll
        for (int t = 0; t < 8; t++) {
            int idx = tid + t * 512;
            int half = idx >= 2048;
            int cc = idx & 2047;
            int row = cc >> 4, q = cc & 15;
            const __nv_bfloat16* src = (half ? Wl2 : Wh2) + (size_t)row * H1 + 128 + q * 8;
            cp16((half ? aWl : aWh) + (uint32_t)((128 + row) * LDA + q * 8) * 2, src);
        }
        CP_COMMIT();
    }

    float acc4[2][4][4];
    #pragma unroll
    for (int i = 0; i < 2; i++)
        #pragma unroll
        for (int j = 0; j < 4; j++)
            #pragma unroll
            for (int q = 0; q < 4; q++) acc4[i][j][q] = 0.f;

    CP_WAIT1();
    __syncthreads();
    mma128(acc4, 0);
    __syncthreads();
    issueAct(1);
    issueW(WhC, WlC, FEAT, 0);
    CP_WAIT1();
    __syncthreads();
    mma128(acc4, 1);
    __syncthreads();
    epilogue(acc4, b2);
    __syncthreads();

    for (int l = 0; l < DEPTH; l++) {
        if (l + 1 < DEPTH)
            issueW(WhC + (size_t)(l + 1) * FEAT * FEAT,
                   WlC + (size_t)(l + 1) * FEAT * FEAT, FEAT, (l + 1) & 1);
        if (l + 1 < DEPTH) { CP_WAIT1(); } else { CP_WAIT0(); }
        __syncthreads();
        #pragma unroll
        for (int i = 0; i < 2; i++)
            #pragma unroll
            for (int j = 0; j < 4; j++)
                #pragma unroll
                for (int q = 0; q < 4; q++) acc4[i][j][q] = 0.f;
        mma128(acc4, l & 1);
        __syncthreads();
        epilogue(acc4, consB + (size_t)l * FEAT);
        __syncthreads();
    }

    issueFin(0);
    CP_WAIT0();
    const float cfac = 0.42f * 1.8f / (float)CAP;
    for (int k = 0; k < NCOND; k++) {
        __syncthreads();
        if (tid < 128) wsum[tid] = 0.f;

        float acc8[2][8][4];
        #pragma unroll
        for (int i = 0; i < 2; i++)
            #pragma unroll
            for (int j = 0; j < 8; j++)
                #pragma unroll
                for (int q = 0; q < 4; q++) acc8[i][j][q] = 0.f;

        #pragma unroll
        for (int ch = 0; ch < 8; ch++) {
            const int colh = ch * 16 + ((lane >> 4) << 3);
            uint32_t a_h[2][4], a_l[2][4], bfr[8][2];
            #pragma unroll
            for (int mt = 0; mt < 2; mt++) {
                int row = wm * 32 + mt * 16 + (lane & 15);
                ldsm4(a_h[mt], aAh + (uint32_t)(row * LDA + colh) * 2);
                ldsm4(a_l[mt], aAl + (uint32_t)(row * LDA + colh) * 2);
            }
            #pragma unroll
            for (int nt2 = 0; nt2 < 4; nt2++) {
                int row = wn * 64 + nt2 * 16 + (lane & 15);
                uint32_t r[4];
                ldsm4(r, aWh + (uint32_t)(row * LDA + colh) * 2);
                bfr[2 * nt2][0] = r[0]; bfr[2 * nt2][1] = r[2];
                bfr[2 * nt2 + 1][0] = r[1]; bfr[2 * nt2 + 1][1] = r[3];
            }
            #pragma unroll
            for (int mt = 0; mt < 2; mt++)
                #pragma unroll
                for (int nt = 0; nt < 8; nt++) mma_bf16(acc8[mt][nt], a_h[mt], bfr[nt]);
            #pragma unroll
            for (int mt = 0; mt < 2; mt++)
                #pragma unroll
                for (int nt = 0; nt < 8; nt++) mma_bf16(acc8[mt][nt], a_l[mt], bfr[nt]);
            #pragma unroll
            for (int nt2 = 0; nt2 < 4; nt2++) {
                int row = wn * 64 + nt2 * 16 + (lane & 15);
                uint32_t r[4];
                ldsm4(r, aWl + (uint32_t)(row * LDA + colh) * 2);
                bfr[2 * nt2][0] = r[0]; bfr[2 * nt2][1] = r[2];
                bfr[2 * nt2 + 1][0] = r[1]; bfr[2 * nt2 + 1][1] = r[3];
            }
            #pragma unroll
            for (int mt = 0; mt < 2; mt++)
                #pragma unroll
                for (int nt = 0; nt < 8; nt++) mma_bf16(acc8[mt][nt], a_h[mt], bfr[nt]);
        }
        __syncthreads();
        if (k + 1 < NCOND) issueFin(k + 1);

        if (wn >= 2) {
            #pragma unroll
            for (int mt = 0; mt < 2; mt++) {
                const int r1 = wm * 32 + mt * 16 + (lane >> 2);
                float p1 = 0.f, p2 = 0.f;
                #pragma unroll
                for (int nt = 0; nt < 8; nt++) {
                    const int e0 = (wn - 2) * 64 + nt * 8 + ((lane & 3) << 1);
                    float m00 = __bfloat162float(sAh[r1 * LDA + e0]) +
                                __bfloat162float(sAl[r1 * LDA + e0]);
                    float m01 = __bfloat162float(sAh[r1 * LDA + e0 + 1]) +
                                __bfloat162float(sAl[r1 * LDA + e0 + 1]);
                    float m10 = __bfloat162float(sAh[(r1 + 8) * LDA + e0]) +
                                __bfloat162float(sAl[(r1 + 8) * LDA + e0]);
                    float m11 = __bfloat162float(sAh[(r1 + 8) * LDA + e0 + 1]) +
                                __bfloat162float(sAl[(r1 + 8) * LDA + e0 + 1]);
                    p1 += acc8[mt][nt][0] * m00 + acc8[mt][nt][1] * m01;
                    p2 += acc8[mt][nt][2] * m10 + acc8[mt][nt][3] * m11;
                }
                atomicAdd(&wsum[r1], p1);
                atomicAdd(&wsum[r1 + 8], p2);
            }
        }
        __syncthreads();
        if (tid < 128) wsum[tid] = wsum[tid] * cfac + 0.3f * saw[tid];
        __syncthreads();

        if (wn < 2) {
            #pragma unroll
            for (int mt = 0; mt < 2; mt++) {
                const int rl = wm * 32 + mt * 16 + (lane >> 2);
                const float w1 = wsum[rl], w2 = wsum[rl + 8];
                #pragma unroll
                for (int nt = 0; nt < 8; nt++) {
                    const int col = wn * 64 + nt * 8 + ((lane & 3) << 1);
                    float2 bv = *(const float2*)(retB + (size_t)k * FEAT + col);
                    size_t base1 = (size_t)(m0 + rl) * (NCOND * FEAT) + (size_t)k * FEAT + col;
                    size_t base2 = (size_t)(m0 + rl + 8) * (NCOND * FEAT) + (size_t)k * FEAT + col;
                    *(float2*)(out + base1) = make_float2((acc8[mt][nt][0] + bv.x) * w1,
                                                          (acc8[mt][nt][1] + bv.y) * w1);
                    *(float2*)(out + base2) = make_float2((acc8[mt][nt][2] + bv.x) * w2,
                                                          (acc8[mt][nt][3] + bv.y) * w2);
                }
            }
        }
        if (k + 1 < NCOND) CP_WAIT0();
    }
}

// ===========================================================================
extern "C" void kernel_launch(void* const* d_in, const int* in_sizes, int n_in,
                              void* d_out, int out_size) {
    const float* sup  = (const float*)d_in[0];
    const float* anom = (const float*)d_in[1];
    const float* ind  = (const float*)d_in[2];
    const float* ipW1 = (const float*)d_in[3];
    const float* ipb1 = (const float*)d_in[4];
    const float* ipW2 = (const float*)d_in[5];
    const float* ipb2 = (const float*)d_in[6];
    const float* consW = (const float*)d_in[7];
    const float* consB = (const float*)d_in[8];
    const float* refp = (const float*)d_in[9];
    const float* objp = (const float*)d_in[10];
    const float* retW = (const float*)d_in[11];
    const float* retB = (const float*)d_in[12];
    float* out = (float*)d_out;

    __nv_bfloat16 *Wh1, *Wl1, *Wh2, *Wl2, *WhC, *WlC, *h1h, *h1l, *WfH, *WfL;
    float *aw;
    cudaGetSymbolAddress((void**)&Wh1, g_Wh1);
    cudaGetSymbolAddress((void**)&Wl1, g_Wl1);
    cudaGetSymbolAddress((void**)&Wh2, g_Wh2);
    cudaGetSymbolAddress((void**)&Wl2, g_Wl2);
    cudaGetSymbolAddress((void**)&WhC, g_WhC);
    cudaGetSymbolAddress((void**)&WlC, g_WlC);
    cudaGetSymbolAddress((void**)&h1h, g_h1h);
    cudaGetSymbolAddress((void**)&h1l, g_h1l);
    cudaGetSymbolAddress((void**)&WfH, g_WfinH);
    cudaGetSymbolAddress((void**)&WfL, g_WfinL);
    cudaGetSymbolAddress((void**)&aw, g_aw);

    cudaFuncSetAttribute(gemm1_v3, cudaFuncAttributeMaxDynamicSharedMemorySize, G3_SMEM);
    cudaFuncSetAttribute(fused_tail, cudaFuncAttributeMaxDynamicSharedMemorySize, TAIL_SMEM);

    // ncu captures kernel_launch's 4th launch (harness issues 2 before ours).
    tsplit_kernel<<<dim3(D_IN / 32, H1 / 32, 1), dim3(32, 8)>>>(ipW1, Wh1, Wl1, D_IN, H1, H1 * D_IN); // 1
    aw_kernel<<<BB * 32 / 256, 256>>>(anom, aw);                                      // 2
    mkfin_kernel<<<NCOND, 256>>>(refp, objp, WfH, WfL);                               // 3
    gemm1_v3<<<dim3(2, BB / 64), 256, G3_SMEM>>>(sup, anom, ind, Wh1, Wl1, ipb1, h1h, h1l); // 4 (profiled)
    tsplit_kernel<<<dim3(H1 / 32, FEAT / 32, 1), dim3(32, 8)>>>(ipW2, Wh2, Wl2, H1, FEAT, FEAT * H1); // 5
    tsplit_kernel<<<dim3(FEAT / 32, FEAT / 32, DEPTH), dim3(32, 8)>>>(consW, WhC, WlC, FEAT, FEAT, FEAT * FEAT); // 6
    tsplit_kernel<<<dim3(FEAT / 32, FEAT / 32, NCOND), dim3(32, 8)>>>(retW, WfH, WfL, FEAT, FEAT, 256 * FEAT);   // 7
    fused_tail<<<BB / 128, 512, TAIL_SMEM>>>(
        h1h, h1l, Wh2, Wl2, ipb2, WhC, WlC, consB, WfH, WfL, retB, aw, out);          // 8
}

// round 12
// speedup vs baseline: 1.6357x; 1.0040x over previous
#include <cuda_runtime.h>
#include <cuda_bf16.h>
#include <stdint.h>

#define BB 16384
#define D_SUP 1024
#define D_ANOM 128
#define D_IND 2048
#define D_IN 3200
#define H1 256
#define FEAT 128
#define DEPTH 12
#define NCOND 14
#define CAP 256

// ---------------- scratch (device globals; no allocation allowed) ----------
__device__ __nv_bfloat16 g_Wh1[H1 * D_IN];           // W1^T hi [256][3200]
__device__ __nv_bfloat16 g_Wl1[H1 * D_IN];
__device__ __nv_bfloat16 g_Wh2[FEAT * H1];           // W2^T hi [128][256]
__device__ __nv_bfloat16 g_Wl2[FEAT * H1];
__device__ __nv_bfloat16 g_WhC[DEPTH * FEAT * FEAT]; // consW^T hi [12][128][128]
__device__ __nv_bfloat16 g_WlC[DEPTH * FEAT * FEAT];
__device__ __nv_bfloat16 g_h1h[BB * H1];             // h1 hi/lo [16384][256]
__device__ __nv_bfloat16 g_h1l[BB * H1];
__device__ __nv_bfloat16 g_WfinH[NCOND * 256 * FEAT]; // [k][256][128]: rows 0-127 retW^T, 128-255 Mk^T
__device__ __nv_bfloat16 g_WfinL[NCOND * 256 * FEAT];
__device__ float g_aw[BB];

// ---------------- helpers --------------------------------------------------
__device__ __forceinline__ uint32_t smem_u32(const void* p) {
    uint32_t a;
    asm("{ .reg .u64 t; cvta.to.shared.u64 t, %1; cvt.u32.u64 %0, t; }" : "=r"(a) : "l"(p));
    return a;
}
__device__ __forceinline__ void ldsm4(uint32_t* r, uint32_t addr) {
    asm volatile("ldmatrix.sync.aligned.m8n8.x4.shared.b16 {%0,%1,%2,%3}, [%4];"
                 : "=r"(r[0]), "=r"(r[1]), "=r"(r[2]), "=r"(r[3]) : "r"(addr));
}
__device__ __forceinline__ void mma_bf16(float* c, const uint32_t* a, const uint32_t* b) {
    asm volatile("mma.sync.aligned.m16n8k16.row.col.f32.bf16.bf16.f32 "
                 "{%0,%1,%2,%3}, {%4,%5,%6,%7}, {%8,%9}, {%0,%1,%2,%3};"
                 : "+f"(c[0]), "+f"(c[1]), "+f"(c[2]), "+f"(c[3])
                 : "r"(a[0]), "r"(a[1]), "r"(a[2]), "r"(a[3]), "r"(b[0]), "r"(b[1]));
}
__device__ __forceinline__ void cp16(uint32_t smem, const void* g) {
    asm volatile("cp.async.cg.shared.global [%0], [%1], 16;" :: "r"(smem), "l"(g));
}
#define CP_COMMIT() asm volatile("cp.async.commit_group;" ::: "memory")
#define CP_WAIT0()  asm volatile("cp.async.wait_group 0;" ::: "memory")
#define CP_WAIT1()  asm volatile("cp.async.wait_group 1;" ::: "memory")

// ---------------- aw[b] = mean(|anomaly[b,:]|) -----------------------------
__global__ __launch_bounds__(256) void aw_kernel(const float* __restrict__ anom,
                                                 float* __restrict__ aw) {
    int warp = (blockIdx.x * blockDim.x + threadIdx.x) >> 5;
    int lane = threadIdx.x & 31;
    if (warp >= BB) return;
    float4 v = *(const float4*)(anom + (size_t)warp * D_ANOM + lane * 4);
    float s = fabsf(v.x) + fabsf(v.y) + fabsf(v.z) + fabsf(v.w);
    #pragma unroll
    for (int o = 16; o; o >>= 1) s += __shfl_xor_sync(0xFFFFFFFFu, s, o);
    if (lane == 0) aw[warp] = s * (1.0f / D_ANOM);
}

// ---------------- Mk^T hi/lo into Wfin rows 128-255 ------------------------
__global__ __launch_bounds__(256) void mkfin_kernel(const float* __restrict__ refp,
                                                    const float* __restrict__ objp,
                                                    __nv_bfloat16* __restrict__ WfH,
                                                    __nv_bfloat16* __restrict__ WfL) {
    const int k = blockIdx.x;
    __shared__ float Rs[32][FEAT];
    __shared__ float Os[32][FEAT];
    const int tid = threadIdx.x;
    const int tc = tid & 15;
    const int tr = tid >> 4;
    float acc[8][8] = {};
    const float* rb = refp + (size_t)k * CAP * FEAT;
    const float* ob = objp + (size_t)k * CAP * FEAT;
    for (int c0 = 0; c0 < CAP; c0 += 32) {
        #pragma unroll
        for (int i = tid; i < 32 * FEAT / 4; i += 256) {
            int c = i >> 5, d4 = (i & 31) * 4;
            *(float4*)&Rs[c][d4] = *(const float4*)(rb + (size_t)(c0 + c) * FEAT + d4);
            *(float4*)&Os[c][d4] = *(const float4*)(ob + (size_t)(c0 + c) * FEAT + d4);
        }
        __syncthreads();
        #pragma unroll 8
        for (int c = 0; c < 32; c++) {
            float a[8], b[8];
            #pragma unroll
            for (int i = 0; i < 8; i += 4) *(float4*)&a[i] = *(const float4*)&Rs[c][tr * 8 + i];
            #pragma unroll
            for (int j = 0; j < 8; j += 4) *(float4*)&b[j] = *(const float4*)&Os[c][tc * 8 + j];
            #pragma unroll
            for (int i = 0; i < 8; i++)
                #pragma unroll
                for (int j = 0; j < 8; j++) acc[i][j] += a[i] * b[j];
        }
        __syncthreads();
    }
    #pragma unroll
    for (int j = 0; j < 8; j++) {
        int e = tc * 8 + j;
        __nv_bfloat16 hv[8], lv[8];
        #pragma unroll
        for (int i = 0; i < 8; i++) {
            float v = acc[i][j];
            __nv_bfloat16 hi = __float2bfloat16(v);
            hv[i] = hi;
            lv[i] = __float2bfloat16(v - __bfloat162float(hi));
        }
        size_t base = (size_t)k * 256 * FEAT + (size_t)(128 + e) * FEAT + tr * 8;
        *(uint4*)(WfH + base) = *(uint4*)hv;
        *(uint4*)(WfL + base) = *(uint4*)lv;
    }
}

// ---------------- transpose + hi/lo split:  dst[n][k] = W[k][n] ------------
__global__ __launch_bounds__(256) void tsplit_kernel(const float* __restrict__ W,
                                                     __nv_bfloat16* __restrict__ Wh,
                                                     __nv_bfloat16* __restrict__ Wl,
                                                     int K, int N, int dstBatchStride) {
    const int batch = blockIdx.z;
    W += (size_t)batch * K * N;
    Wh += (size_t)batch * dstBatchStride;
    Wl += (size_t)batch * dstBatchStride;
    __shared__ float t[32][33];
    const int k0 = blockIdx.x * 32;
    const int n0 = blockIdx.y * 32;
    const int tx = threadIdx.x, ty = threadIdx.y;
    #pragma unroll
    for (int i = 0; i < 4; i++)
        t[ty + 8 * i][tx] = W[(size_t)(k0 + ty + 8 * i) * N + n0 + tx];
    __syncthreads();
    #pragma unroll
    for (int i = 0; i < 4; i++) {
        int n = n0 + ty + 8 * i;
        int k = k0 + tx;
        float v = t[tx][ty + 8 * i];
        __nv_bfloat16 hi = __float2bfloat16(v);
        __nv_bfloat16 lo = __float2bfloat16(v - __bfloat162float(hi));
        Wh[(size_t)n * K + k] = hi;
        Wl[(size_t)n * K + k] = lo;
    }
}

// ===========================================================================
// GEMM1 v4: BM=64, BN=128, 256 threads, in-place fp32->bf16 conversion,
// 30720B/buffer -> 61440B total -> 3 CTAs/SM.
//   A region [0,10240): cp.async lands fp32 (stride 144, 9216B footprint);
//   after reg-staged convert it holds bf16 hi [0,5120) + lo [5120,10240).
// ===========================================================================
#define G4_OA  0
#define G4_OWH 10240
#define G4_OWL 20480
#define G4_BUF 30720
#define G4_SMEM (2 * G4_BUF)
#define G4_NIT (D_IN / 32)

__global__ __launch_bounds__(256, 3) void gemm1_v4(
    const float* __restrict__ A0, const float* __restrict__ A1,
    const float* __restrict__ A2,
    const __nv_bfloat16* __restrict__ Bh, const __nv_bfloat16* __restrict__ Bl,
    const float* __restrict__ bias,
    __nv_bfloat16* __restrict__ Oh, __nv_bfloat16* __restrict__ Ol) {
    extern __shared__ char sm[];
    const uint32_t sb = smem_u32(sm);
    const int tid = threadIdx.x;
    const int wid = tid >> 5, lane = tid & 31;
    const int warpM = (wid & 1) * 32;
    const int warpN = (wid >> 1) * 32;
    const int n0 = blockIdx.x * 128;
    const int m0 = blockIdx.y * 64;

    float acc[2][4][4];
    #pragma unroll
    for (int i = 0; i < 2; i++)
        #pragma unroll
        for (int j = 0; j < 4; j++)
            #pragma unroll
            for (int q = 0; q < 4; q++) acc[i][j][q] = 0.f;

    auto issue = [&](int it, int b) {
        const int k0 = it * 32;
        const float* Ap; int lda, kk;
        if (k0 < D_SUP)               { Ap = A0; lda = D_SUP;  kk = k0; }
        else if (k0 < D_SUP + D_ANOM) { Ap = A1; lda = D_ANOM; kk = k0 - D_SUP; }
        else                          { Ap = A2; lda = D_IND;  kk = k0 - D_SUP - D_ANOM; }
        const uint32_t bb = sb + b * G4_BUF;
        #pragma unroll
        for (int t = 0; t < 2; t++) {
            int idx = tid + t * 256;          // 512 float4 chunks of A (fp32, stride 144)
            int row = idx >> 3, q = idx & 7;
            cp16(bb + G4_OA + row * 144 + q * 16,
                 Ap + (size_t)(m0 + row) * lda + kk + q * 4);
        }
        #pragma unroll
        for (int t = 0; t < 4; t++) {
            int idx = tid + t * 256;          // 1024 chunks of W (hi then lo)
            int plane = idx >= 512;
            int cc = idx & 511;
            int row = cc >> 2, q = cc & 3;
            cp16(bb + (plane ? G4_OWL : G4_OWH) + row * 80 + q * 16,
                 (plane ? Bl : Bh) + (size_t)(n0 + row) * D_IN + k0 + q * 8);
        }
        CP_COMMIT();
    };

    issue(0, 0);

    for (int it = 0; it < G4_NIT; it++) {
        const int b = it & 1;
        const uint32_t bb = sb + b * G4_BUF;
        CP_WAIT0();
        __syncthreads();
        if (it + 1 < G4_NIT) issue(it + 1, b ^ 1);

        // in-place convert: stage fp32 to regs, sync, overwrite region with hi/lo
        float4 v[2];
        #pragma unroll
        for (int t = 0; t < 2; t++) {
            int idx = tid + t * 256;
            int row = idx >> 3, q = idx & 7;
            v[t] = *(const float4*)(sm + (size_t)b * G4_BUF + G4_OA + row * 144 + q * 16);
        }
        __syncthreads();
        #pragma unroll
        for (int t = 0; t < 2; t++) {
            int idx = tid + t * 256;
            int row = idx >> 3, q = idx & 7;
            __nv_bfloat16 hx = __float2bfloat16(v[t].x), hy = __float2bfloat16(v[t].y);
            __nv_bfloat16 hz = __float2bfloat16(v[t].z), hw = __float2bfloat16(v[t].w);
            __nv_bfloat162 h01 = {hx, hy}, h23 = {hz, hw};
            __nv_bfloat162 l01 = __floats2bfloat162_rn(v[t].x - __bfloat162float(hx),
                                                       v[t].y - __bfloat162float(hy));
            __nv_bfloat162 l23 = __floats2bfloat162_rn(v[t].z - __bfloat162float(hz),
                                                       v[t].w - __bfloat162float(hw));
            size_t off = (size_t)b * G4_BUF + G4_OA + row * 80 + q * 8;
            *(__nv_bfloat162*)(sm + off) = h01;
            *(__nv_bfloat162*)(sm + off + 4) = h23;
            *(__nv_bfloat162*)(sm + off + 5120) = l01;
            *(__nv_bfloat162*)(sm + off + 5120 + 4) = l23;
        }
        __syncthreads();

        #pragma unroll
        for (int kq = 0; kq < 2; kq++) {
            const uint32_t colb = (uint32_t)(kq * 16 + ((lane >> 4) << 3)) * 2;
            uint32_t a_h[2][4], a_l[2][4], bfr[4][2];
            #pragma unroll
            for (int mt = 0; mt < 2; mt++) {
                uint32_t off = (uint32_t)(warpM + mt * 16 + (lane & 15)) * 80 + colb;
                ldsm4(a_h[mt], bb + G4_OA + off);
                ldsm4(a_l[mt], bb + G4_OA + 5120 + off);
            }
            #pragma unroll
            for (int nt2 = 0; nt2 < 2; nt2++) {
                uint32_t off = (uint32_t)(warpN + nt2 * 16 + (lane & 15)) * 80 + colb;
                uint32_t r[4];
                ldsm4(r, bb + G4_OWH + off);
                bfr[2 * nt2][0] = r[0]; bfr[2 * nt2][1] = r[2];
                bfr[2 * nt2 + 1][0] = r[1]; bfr[2 * nt2 + 1][1] = r[3];
            }
            #pragma unroll
            for (int mt = 0; mt < 2; mt++)
                #pragma unroll
                for (int nt = 0; nt < 4; nt++) mma_bf16(acc[mt][nt], a_h[mt], bfr[nt]);
            #pragma unroll
            for (int mt = 0; mt < 2; mt++)
                #pragma unroll
                for (int nt = 0; nt < 4; nt++) mma_bf16(acc[mt][nt], a_l[mt], bfr[nt]);
            #pragma unroll
            for (int nt2 = 0; nt2 < 2; nt2++) {
                uint32_t off = (uint32_t)(warpN + nt2 * 16 + (lane & 15)) * 80 + colb;
                uint32_t r[4];
                ldsm4(r, bb + G4_OWL + off);
                bfr[2 * nt2][0] = r[0]; bfr[2 * nt2][1] = r[2];
                bfr[2 * nt2 + 1][0] = r[1]; bfr[2 * nt2 + 1][1] = r[3];
            }
            #pragma unroll
            for (int mt = 0; mt < 2; mt++)
                #pragma unroll
                for (int nt = 0; nt < 4; nt++) mma_bf16(acc[mt][nt], a_h[mt], bfr[nt]);
        }
    }

    // epilogue: bias + relu -> bf16 hi/lo
    #pragma unroll
    for (int mt = 0; mt < 2; mt++) {
        const int r0 = m0 + warpM + mt * 16 + (lane >> 2);
        #pragma unroll
        for (int nt = 0; nt < 4; nt++) {
            const int ng = n0 + warpN + nt * 8 + ((lane & 3) << 1);
            float2 bv = *(const float2*)(bias + ng);
            float v00 = fmaxf(acc[mt][nt][0] + bv.x, 0.f);
            float v01 = fmaxf(acc[mt][nt][1] + bv.y, 0.f);
            float v10 = fmaxf(acc[mt][nt][2] + bv.x, 0.f);
            float v11 = fmaxf(acc[mt][nt][3] + bv.y, 0.f);
            __nv_bfloat16 h00 = __float2bfloat16(v00), h01 = __float2bfloat16(v01);
            __nv_bfloat16 h10 = __float2bfloat16(v10), h11 = __float2bfloat16(v11);
            __nv_bfloat162 hi0 = {h00, h01}, hi1 = {h10, h11};
            __nv_bfloat162 lo0 = __floats2bfloat162_rn(v00 - __bfloat162float(h00),
                                                       v01 - __bfloat162float(h01));
            __nv_bfloat162 lo1 = __floats2bfloat162_rn(v10 - __bfloat162float(h10),
                                                       v11 - __bfloat162float(h11));
            *(__nv_bfloat162*)(Oh + (size_t)r0 * H1 + ng) = hi0;
            *(__nv_bfloat162*)(Ol + (size_t)r0 * H1 + ng) = lo0;
            *(__nv_bfloat162*)(Oh + (size_t)(r0 + 8) * H1 + ng) = hi1;
            *(__nv_bfloat162*)(Ol + (size_t)(r0 + 8) * H1 + ng) = lo1;
        }
    }
}

// ===========================================================================
// Fused tail (unchanged): GEMM2 + 12 layers + final retrieval.
// ===========================================================================
#define LDA 136
#define TAIL_SMEM ((128 * LDA * 2 + 256 * LDA * 2) * 2 + 256 * 4)

__global__ __launch_bounds__(512, 1) void fused_tail(
    const __nv_bfloat16* __restrict__ h1h, const __nv_bfloat16* __restrict__ h1l,
    const __nv_bfloat16* __restrict__ Wh2, const __nv_bfloat16* __restrict__ Wl2,
    const float* __restrict__ b2,
    const __nv_bfloat16* __restrict__ WhC, const __nv_bfloat16* __restrict__ WlC,
    const float* __restrict__ consB,
    const __nv_bfloat16* __restrict__ WfH, const __nv_bfloat16* __restrict__ WfL,
    const float* __restrict__ retB, const float* __restrict__ aw,
    float* __restrict__ out) {
    extern __shared__ __nv_bfloat16 smt[];
    __nv_bfloat16* sAh = smt;
    __nv_bfloat16* sAl = sAh + 128 * LDA;
    __nv_bfloat16* sWh = sAl + 128 * LDA;
    __nv_bfloat16* sWl = sWh + 256 * LDA;
    float* wsum = (float*)(sWl + 256 * LDA);
    float* saw  = wsum + 128;

    const int tid = threadIdx.x;
    const int wid = tid >> 5, lane = tid & 31;
    const int wm = wid & 3;
    const int wn = wid >> 2;
    const int m0 = blockIdx.x * 128;

    const uint32_t aAh = smem_u32(sAh), aAl = smem_u32(sAl);
    const uint32_t aWh = smem_u32(sWh), aWl = smem_u32(sWl);

    auto issueW = [&](const __nv_bfloat16* srcH, const __nv_bfloat16* srcL,
                      int srcStride, int slot) {
        #pragma unroll
        for (int t = 0; t < 8; t++) {
            int idx = tid + t * 512;
            int half = idx >= 2048;
            int cc = idx & 2047;
            int row = cc >> 4, q = cc & 15;
            const __nv_bfloat16* src = (half ? srcL : srcH) + (size_t)row * srcStride + q * 8;
            cp16((half ? aWl : aWh) + (uint32_t)((slot * 128 + row) * LDA + q * 8) * 2, src);
        }
        CP_COMMIT();
    };
    auto issueAct = [&](int kc) {
        #pragma unroll
        for (int t = 0; t < 8; t++) {
            int idx = tid + t * 512;
            int half = idx >= 2048;
            int cc = idx & 2047;
            int row = cc >> 4, q = cc & 15;
            const __nv_bfloat16* src = (half ? h1l : h1h)
                + (size_t)(m0 + row) * H1 + kc * 128 + q * 8;
            cp16((half ? aAl : aAh) + (uint32_t)(row * LDA + q * 8) * 2, src);
        }
        CP_COMMIT();
    };
    auto issueFin = [&](int k) {
        #pragma unroll
        for (int t = 0; t < 16; t++) {
            int idx = tid + t * 512;
            int half = idx >= 4096;
            int cc = idx & 4095;
            int row = cc >> 4, q = cc & 15;
            const __nv_bfloat16* src = (half ? WfL : WfH)
                + (size_t)k * 256 * FEAT + (size_t)row * FEAT + q * 8;
            cp16((half ? aWl : aWh) + (uint32_t)(row * LDA + q * 8) * 2, src);
        }
        CP_COMMIT();
    };

    auto mma128 = [&](float acc4[2][4][4], int slot) {
        const uint32_t base = (uint32_t)(slot * 128 * LDA) * 2;
        #pragma unroll
        for (int ch = 0; ch < 8; ch++) {
            const int colh = ch * 16 + ((lane >> 4) << 3);
            uint32_t a_h[2][4], a_l[2][4], bfr[4][2];
            #pragma unroll
            for (int mt = 0; mt < 2; mt++) {
                int row = wm * 32 + mt * 16 + (lane & 15);
                ldsm4(a_h[mt], aAh + (uint32_t)(row * LDA + colh) * 2);
                ldsm4(a_l[mt], aAl + (uint32_t)(row * LDA + colh) * 2);
            }
            #pragma unroll
            for (int nt2 = 0; nt2 < 2; nt2++) {
                int row = wn * 32 + nt2 * 16 + (lane & 15);
                uint32_t r[4];
                ldsm4(r, aWh + base + (uint32_t)(row * LDA + colh) * 2);
                bfr[2 * nt2][0] = r[0]; bfr[2 * nt2][1] = r[2];
                bfr[2 * nt2 + 1][0] = r[1]; bfr[2 * nt2 + 1][1] = r[3];
            }
            #pragma unroll
            for (int mt = 0; mt < 2; mt++)
                #pragma unroll
                for (int nt = 0; nt < 4; nt++) mma_bf16(acc4[mt][nt], a_h[mt], bfr[nt]);
            #pragma unroll
            for (int mt = 0; mt < 2; mt++)
                #pragma unroll
                for (int nt = 0; nt < 4; nt++) mma_bf16(acc4[mt][nt], a_l[mt], bfr[nt]);
            #pragma unroll
            for (int nt2 = 0; nt2 < 2; nt2++) {
                int row = wn * 32 + nt2 * 16 + (lane & 15);
                uint32_t r[4];
                ldsm4(r, aWl + base + (uint32_t)(row * LDA + colh) * 2);
                bfr[2 * nt2][0] = r[0]; bfr[2 * nt2][1] = r[2];
                bfr[2 * nt2 + 1][0] = r[1]; bfr[2 * nt2 + 1][1] = r[3];
            }
            #pragma unroll
            for (int mt = 0; mt < 2; mt++)
                #pragma unroll
                for (int nt = 0; nt < 4; nt++) mma_bf16(acc4[mt][nt], a_h[mt], bfr[nt]);
        }
    };
    auto epilogue = [&](float acc4[2][4][4], const float* biasp) {
        #pragma unroll
        for (int mt = 0; mt < 2; mt++) {
            const int row = wm * 32 + mt * 16 + (lane >> 2);
            #pragma unroll
            for (int nt = 0; nt < 4; nt++) {
                const int col = wn * 32 + nt * 8 + ((lane & 3) << 1);
                float2 bv = *(const float2*)(biasp + col);
                float v00 = fmaxf(acc4[mt][nt][0] + bv.x, 0.f);
                float v01 = fmaxf(acc4[mt][nt][1] + bv.y, 0.f);
                float v10 = fmaxf(acc4[mt][nt][2] + bv.x, 0.f);
                float v11 = fmaxf(acc4[mt][nt][3] + bv.y, 0.f);
                __nv_bfloat16 h00 = __float2bfloat16(v00), h01 = __float2bfloat16(v01);
                __nv_bfloat16 h10 = __float2bfloat16(v10), h11 = __float2bfloat16(v11);
                __nv_bfloat162 hi0 = {h00, h01}, hi1 = {h10, h11};
                __nv_bfloat162 lo0 = __floats2bfloat162_rn(v00 - __bfloat162float(h00),
                                                           v01 - __bfloat162float(h01));
                __nv_bfloat162 lo1 = __floats2bfloat162_rn(v10 - __bfloat162float(h10),
                                                           v11 - __bfloat162float(h11));
                *(__nv_bfloat162*)(sAh + row * LDA + col) = hi0;
                *(__nv_bfloat162*)(sAl + row * LDA + col) = lo0;
                *(__nv_bfloat162*)(sAh + (row + 8) * LDA + col) = hi1;
                *(__nv_bfloat162*)(sAl + (row + 8) * LDA + col) = lo1;
            }
        }
    };

    if (tid < 128) saw[tid] = aw[m0 + tid];

    issueW(Wh2, Wl2, H1, 0);
    issueAct(0);
    {
        #pragma unroll
        for (int t = 0; t < 8; t++) {
            int idx = tid + t * 512;
            int half = idx >= 2048;
            int cc = idx & 2047;
            int row = cc >> 4, q = cc & 15;
            const __nv_bfloat16* src = (half ? Wl2 : Wh2) + (size_t)row * H1 + 128 + q * 8;
            cp16((half ? aWl : aWh) + (uint32_t)((128 + row) * LDA + q * 8) * 2, src);
        }
        CP_COMMIT();
    }

    float acc4[2][4][4];
    #pragma unroll
    for (int i = 0; i < 2; i++)
        #pragma unroll
        for (int j = 0; j < 4; j++)
            #pragma unroll
            for (int q = 0; q < 4; q++) acc4[i][j][q] = 0.f;

    CP_WAIT1();
    __syncthreads();
    mma128(acc4, 0);
    __syncthreads();
    issueAct(1);
    issueW(WhC, WlC, FEAT, 0);
    CP_WAIT1();
    __syncthreads();
    mma128(acc4, 1);
    __syncthreads();
    epilogue(acc4, b2);
    __syncthreads();

    for (int l = 0; l < DEPTH; l++) {
        if (l + 1 < DEPTH)
            issueW(WhC + (size_t)(l + 1) * FEAT * FEAT,
                   WlC + (size_t)(l + 1) * FEAT * FEAT, FEAT, (l + 1) & 1);
        if (l + 1 < DEPTH) { CP_WAIT1(); } else { CP_WAIT0(); }
        __syncthreads();
        #pragma unroll
        for (int i = 0; i < 2; i++)
            #pragma unroll
            for (int j = 0; j < 4; j++)
                #pragma unroll
                for (int q = 0; q < 4; q++) acc4[i][j][q] = 0.f;
        mma128(acc4, l & 1);
        __syncthreads();
        epilogue(acc4, consB + (size_t)l * FEAT);
        __syncthreads();
    }

    issueFin(0);
    CP_WAIT0();
    const float cfac = 0.42f * 1.8f / (float)CAP;
    for (int k = 0; k < NCOND; k++) {
        __syncthreads();
        if (tid < 128) wsum[tid] = 0.f;

        float acc8[2][8][4];
        #pragma unroll
        for (int i = 0; i < 2; i++)
            #pragma unroll
            for (int j = 0; j < 8; j++)
                #pragma unroll
                for (int q = 0; q < 4; q++) acc8[i][j][q] = 0.f;

        #pragma unroll
        for (int ch = 0; ch < 8; ch++) {
            const int colh = ch * 16 + ((lane >> 4) << 3);
            uint32_t a_h[2][4], a_l[2][4], bfr[8][2];
            #pragma unroll
            for (int mt = 0; mt < 2; mt++) {
                int row = wm * 32 + mt * 16 + (lane & 15);
                ldsm4(a_h[mt], aAh + (uint32_t)(row * LDA + colh) * 2);
                ldsm4(a_l[mt], aAl + (uint32_t)(row * LDA + colh) * 2);
            }
            #pragma unroll
            for (int nt2 = 0; nt2 < 4; nt2++) {
                int row = wn * 64 + nt2 * 16 + (lane & 15);
                uint32_t r[4];
                ldsm4(r, aWh + (uint32_t)(row * LDA + colh) * 2);
                bfr[2 * nt2][0] = r[0]; bfr[2 * nt2][1] = r[2];
                bfr[2 * nt2 + 1][0] = r[1]; bfr[2 * nt2 + 1][1] = r[3];
            }
            #pragma unroll
            for (int mt = 0; mt < 2; mt++)
                #pragma unroll
                for (int nt = 0; nt < 8; nt++) mma_bf16(acc8[mt][nt], a_h[mt], bfr[nt]);
            #pragma unroll
            for (int mt = 0; mt < 2; mt++)
                #pragma unroll
                for (int nt = 0; nt < 8; nt++) mma_bf16(acc8[mt][nt], a_l[mt], bfr[nt]);
            #pragma unroll
            for (int nt2 = 0; nt2 < 4; nt2++) {
                int row = wn * 64 + nt2 * 16 + (lane & 15);
                uint32_t r[4];
                ldsm4(r, aWl + (uint32_t)(row * LDA + colh) * 2);
                bfr[2 * nt2][0] = r[0]; bfr[2 * nt2][1] = r[2];
                bfr[2 * nt2 + 1][0] = r[1]; bfr[2 * nt2 + 1][1] = r[3];
            }
            #pragma unroll
            for (int mt = 0; mt < 2; mt++)
                #pragma unroll
                for (int nt = 0; nt < 8; nt++) mma_bf16(acc8[mt][nt], a_h[mt], bfr[nt]);
        }
        __syncthreads();
        if (k + 1 < NCOND) issueFin(k + 1);

        if (wn >= 2) {
            #pragma unroll
            for (int mt = 0; mt < 2; mt++) {
                const int r1 = wm * 32 + mt * 16 + (lane >> 2);
                float p1 = 0.f, p2 = 0.f;
                #pragma unroll
                for (int nt = 0; nt < 8; nt++) {
                    const int e0 = (wn - 2) * 64 + nt * 8 + ((lane & 3) << 1);
                    float m00 = __bfloat162float(sAh[r1 * LDA + e0]) +
                                __bfloat162float(sAl[r1 * LDA + e0]);
                    float m01 = __bfloat162float(sAh[r1 * LDA + e0 + 1]) +
                                __bfloat162float(sAl[r1 * LDA + e0 + 1]);
                    float m10 = __bfloat162float(sAh[(r1 + 8) * LDA + e0]) +
                                __bfloat162float(sAl[(r1 + 8) * LDA + e0]);
                    float m11 = __bfloat162float(sAh[(r1 + 8) * LDA + e0 + 1]) +
                                __bfloat162float(sAl[(r1 + 8) * LDA + e0 + 1]);
                    p1 += acc8[mt][nt][0] * m00 + acc8[mt][nt][1] * m01;
                    p2 += acc8[mt][nt][2] * m10 + acc8[mt][nt][3] * m11;
                }
                atomicAdd(&wsum[r1], p1);
                atomicAdd(&wsum[r1 + 8], p2);
            }
        }
        __syncthreads();
        if (tid < 128) wsum[tid] = wsum[tid] * cfac + 0.3f * saw[tid];
        __syncthreads();

        if (wn < 2) {
            #pragma unroll
            for (int mt = 0; mt < 2; mt++) {
                const int rl = wm * 32 + mt * 16 + (lane >> 2);
                const float w1 = wsum[rl], w2 = wsum[rl + 8];
                #pragma unroll
                for (int nt = 0; nt < 8; nt++) {
                    const int col = wn * 64 + nt * 8 + ((lane & 3) << 1);
                    float2 bv = *(const float2*)(retB + (size_t)k * FEAT + col);
                    size_t base1 = (size_t)(m0 + rl) * (NCOND * FEAT) + (size_t)k * FEAT + col;
                    size_t base2 = (size_t)(m0 + rl + 8) * (NCOND * FEAT) + (size_t)k * FEAT + col;
                    *(float2*)(out + base1) = make_float2((acc8[mt][nt][0] + bv.x) * w1,
                                                          (acc8[mt][nt][1] + bv.y) * w1);
                    *(float2*)(out + base2) = make_float2((acc8[mt][nt][2] + bv.x) * w2,
                                                          (acc8[mt][nt][3] + bv.y) * w2);
                }
            }
        }
        if (k + 1 < NCOND) CP_WAIT0();
    }
}

// ===========================================================================
extern "C" void kernel_launch(void* const* d_in, const int* in_sizes, int n_in,
                              void* d_out, int out_size) {
    const float* sup  = (const float*)d_in[0];
    const float* anom = (const float*)d_in[1];
    const float* ind  = (const float*)d_in[2];
    const float* ipW1 = (const float*)d_in[3];
    const float* ipb1 = (const float*)d_in[4];
    const float* ipW2 = (const float*)d_in[5];
    const float* ipb2 = (const float*)d_in[6];
    const float* consW = (const float*)d_in[7];
    const float* consB = (const float*)d_in[8];
    const float* refp = (const float*)d_in[9];
    const float* objp = (const float*)d_in[10];
    const float* retW = (const float*)d_in[11];
    const float* retB = (const float*)d_in[12];
    float* out = (float*)d_out;

    __nv_bfloat16 *Wh1, *Wl1, *Wh2, *Wl2, *WhC, *WlC, *h1h, *h1l, *WfH, *WfL;
    float *aw;
    cudaGetSymbolAddress((void**)&Wh1, g_Wh1);
    cudaGetSymbolAddress((void**)&Wl1, g_Wl1);
    cudaGetSymbolAddress((void**)&Wh2, g_Wh2);
    cudaGetSymbolAddress((void**)&Wl2, g_Wl2);
    cudaGetSymbolAddress((void**)&WhC, g_WhC);
    cudaGetSymbolAddress((void**)&WlC, g_WlC);
    cudaGetSymbolAddress((void**)&h1h, g_h1h);
    cudaGetSymbolAddress((void**)&h1l, g_h1l);
    cudaGetSymbolAddress((void**)&WfH, g_WfinH);
    cudaGetSymbolAddress((void**)&WfL, g_WfinL);
    cudaGetSymbolAddress((void**)&aw, g_aw);

    cudaFuncSetAttribute(gemm1_v4, cudaFuncAttributeMaxDynamicSharedMemorySize, G4_SMEM);
    cudaFuncSetAttribute(fused_tail, cudaFuncAttributeMaxDynamicSharedMemorySize, TAIL_SMEM);

    // ncu captures kernel_launch's 4th launch (harness issues 2 before ours).
    tsplit_kernel<<<dim3(D_IN / 32, H1 / 32, 1), dim3(32, 8)>>>(ipW1, Wh1, Wl1, D_IN, H1, H1 * D_IN); // 1
    aw_kernel<<<BB * 32 / 256, 256>>>(anom, aw);                                      // 2
    mkfin_kernel<<<NCOND, 256>>>(refp, objp, WfH, WfL);                               // 3
    gemm1_v4<<<dim3(2, BB / 64), 256, G4_SMEM>>>(sup, anom, ind, Wh1, Wl1, ipb1, h1h, h1l); // 4 (profiled)
    tsplit_kernel<<<dim3(H1 / 32, FEAT / 32, 1), dim3(32, 8)>>>(ipW2, Wh2, Wl2, H1, FEAT, FEAT * H1); // 5
    tsplit_kernel<<<dim3(FEAT / 32, FEAT / 32, DEPTH), dim3(32, 8)>>>(consW, WhC, WlC, FEAT, FEAT, FEAT * FEAT); // 6
    tsplit_kernel<<<dim3(FEAT / 32, FEAT / 32, NCOND), dim3(32, 8)>>>(retW, WfH, WfL, FEAT, FEAT, 256 * FEAT);   // 7
    fused_tail<<<BB / 128, 512, TAIL_SMEM>>>(
        h1h, h1l, Wh2, Wl2, ipb2, WhC, WlC, consB, WfH, WfL, retB, aw, out);          // 8
}

// round 13
// speedup vs baseline: 1.7169x; 1.0496x over previous
#include <cuda_runtime.h>
#include <cuda_bf16.h>
#include <stdint.h>

#define BB 16384
#define D_SUP 1024
#define D_ANOM 128
#define D_IND 2048
#define D_IN 3200
#define H1 256
#define FEAT 128
#define DEPTH 12
#define NCOND 14
#define CAP 256

// ---------------- scratch (device globals; no allocation allowed) ----------
__device__ __nv_bfloat16 g_Wh1[H1 * D_IN];           // W1^T hi [256][3200]
__device__ __nv_bfloat16 g_Wl1[H1 * D_IN];
__device__ __nv_bfloat16 g_Wh2[FEAT * H1];           // W2^T hi [128][256]
__device__ __nv_bfloat16 g_Wl2[FEAT * H1];
__device__ __nv_bfloat16 g_WhC[DEPTH * FEAT * FEAT]; // consW^T hi [12][128][128]
__device__ __nv_bfloat16 g_WlC[DEPTH * FEAT * FEAT];
__device__ __nv_bfloat16 g_h1h[BB * H1];             // h1 hi/lo [16384][256]
__device__ __nv_bfloat16 g_h1l[BB * H1];
__device__ __nv_bfloat16 g_WfinH[NCOND * 256 * FEAT]; // [k][256][128]: rows 0-127 retW^T, 128-255 Mk^T
__device__ __nv_bfloat16 g_WfinL[NCOND * 256 * FEAT];
__device__ float g_aw[BB];

// ---------------- helpers --------------------------------------------------
__device__ __forceinline__ uint32_t smem_u32(const void* p) {
    uint32_t a;
    asm("{ .reg .u64 t; cvta.to.shared.u64 t, %1; cvt.u32.u64 %0, t; }" : "=r"(a) : "l"(p));
    return a;
}
__device__ __forceinline__ void ldsm4(uint32_t* r, uint32_t addr) {
    asm volatile("ldmatrix.sync.aligned.m8n8.x4.shared.b16 {%0,%1,%2,%3}, [%4];"
                 : "=r"(r[0]), "=r"(r[1]), "=r"(r[2]), "=r"(r[3]) : "r"(addr));
}
__device__ __forceinline__ void mma_bf16(float* c, const uint32_t* a, const uint32_t* b) {
    asm volatile("mma.sync.aligned.m16n8k16.row.col.f32.bf16.bf16.f32 "
                 "{%0,%1,%2,%3}, {%4,%5,%6,%7}, {%8,%9}, {%0,%1,%2,%3};"
                 : "+f"(c[0]), "+f"(c[1]), "+f"(c[2]), "+f"(c[3])
                 : "r"(a[0]), "r"(a[1]), "r"(a[2]), "r"(a[3]), "r"(b[0]), "r"(b[1]));
}
__device__ __forceinline__ void cp16(uint32_t smem, const void* g) {
    asm volatile("cp.async.cg.shared.global [%0], [%1], 16;" :: "r"(smem), "l"(g));
}
#define CP_COMMIT() asm volatile("cp.async.commit_group;" ::: "memory")
#define CP_WAIT0()  asm volatile("cp.async.wait_group 0;" ::: "memory")
#define CP_WAIT1()  asm volatile("cp.async.wait_group 1;" ::: "memory")

// ---------------- aw[b] = mean(|anomaly[b,:]|) -----------------------------
__global__ __launch_bounds__(256) void aw_kernel(const float* __restrict__ anom,
                                                 float* __restrict__ aw) {
    int warp = (blockIdx.x * blockDim.x + threadIdx.x) >> 5;
    int lane = threadIdx.x & 31;
    if (warp >= BB) return;
    float4 v = *(const float4*)(anom + (size_t)warp * D_ANOM + lane * 4);
    float s = fabsf(v.x) + fabsf(v.y) + fabsf(v.z) + fabsf(v.w);
    #pragma unroll
    for (int o = 16; o; o >>= 1) s += __shfl_xor_sync(0xFFFFFFFFu, s, o);
    if (lane == 0) aw[warp] = s * (1.0f / D_ANOM);
}

// ---------------- Mk^T hi/lo into Wfin rows 128-255 ------------------------
__global__ __launch_bounds__(256) void mkfin_kernel(const float* __restrict__ refp,
                                                    const float* __restrict__ objp,
                                                    __nv_bfloat16* __restrict__ WfH,
                                                    __nv_bfloat16* __restrict__ WfL) {
    const int k = blockIdx.x;
    __shared__ float Rs[32][FEAT];
    __shared__ float Os[32][FEAT];
    const int tid = threadIdx.x;
    const int tc = tid & 15;
    const int tr = tid >> 4;
    float acc[8][8] = {};
    const float* rb = refp + (size_t)k * CAP * FEAT;
    const float* ob = objp + (size_t)k * CAP * FEAT;
    for (int c0 = 0; c0 < CAP; c0 += 32) {
        #pragma unroll
        for (int i = tid; i < 32 * FEAT / 4; i += 256) {
            int c = i >> 5, d4 = (i & 31) * 4;
            *(float4*)&Rs[c][d4] = *(const float4*)(rb + (size_t)(c0 + c) * FEAT + d4);
            *(float4*)&Os[c][d4] = *(const float4*)(ob + (size_t)(c0 + c) * FEAT + d4);
        }
        __syncthreads();
        #pragma unroll 8
        for (int c = 0; c < 32; c++) {
            float a[8], b[8];
            #pragma unroll
            for (int i = 0; i < 8; i += 4) *(float4*)&a[i] = *(const float4*)&Rs[c][tr * 8 + i];
            #pragma unroll
            for (int j = 0; j < 8; j += 4) *(float4*)&b[j] = *(const float4*)&Os[c][tc * 8 + j];
            #pragma unroll
            for (int i = 0; i < 8; i++)
                #pragma unroll
                for (int j = 0; j < 8; j++) acc[i][j] += a[i] * b[j];
        }
        __syncthreads();
    }
    #pragma unroll
    for (int j = 0; j < 8; j++) {
        int e = tc * 8 + j;
        __nv_bfloat16 hv[8], lv[8];
        #pragma unroll
        for (int i = 0; i < 8; i++) {
            float v = acc[i][j];
            __nv_bfloat16 hi = __float2bfloat16(v);
            hv[i] = hi;
            lv[i] = __float2bfloat16(v - __bfloat162float(hi));
        }
        size_t base = (size_t)k * 256 * FEAT + (size_t)(128 + e) * FEAT + tr * 8;
        *(uint4*)(WfH + base) = *(uint4*)hv;
        *(uint4*)(WfL + base) = *(uint4*)lv;
    }
}

// ---------------- transpose + hi/lo split:  dst[n][k] = W[k][n] ------------
__global__ __launch_bounds__(256) void tsplit_kernel(const float* __restrict__ W,
                                                     __nv_bfloat16* __restrict__ Wh,
                                                     __nv_bfloat16* __restrict__ Wl,
                                                     int K, int N, int dstBatchStride) {
    const int batch = blockIdx.z;
    W += (size_t)batch * K * N;
    Wh += (size_t)batch * dstBatchStride;
    Wl += (size_t)batch * dstBatchStride;
    __shared__ float t[32][33];
    const int k0 = blockIdx.x * 32;
    const int n0 = blockIdx.y * 32;
    const int tx = threadIdx.x, ty = threadIdx.y;
    #pragma unroll
    for (int i = 0; i < 4; i++)
        t[ty + 8 * i][tx] = W[(size_t)(k0 + ty + 8 * i) * N + n0 + tx];
    __syncthreads();
    #pragma unroll
    for (int i = 0; i < 4; i++) {
        int n = n0 + ty + 8 * i;
        int k = k0 + tx;
        float v = t[tx][ty + 8 * i];
        __nv_bfloat16 hi = __float2bfloat16(v);
        __nv_bfloat16 lo = __float2bfloat16(v - __bfloat162float(hi));
        Wh[(size_t)n * K + k] = hi;
        Wl[(size_t)n * K + k] = lo;
    }
}

// ===========================================================================
// GEMM1 v5: BM=64, BN=64, 256 threads, 20480B/buffer -> 4 CTAs/SM, 1024 CTAs.
//   A region [0,10240): cp.async fp32 (stride 144); after convert bf16 hi
//   [0,5120) + lo [5120,10240). W hi [10240,15360), lo [15360,20480).
//   8 warps, warp tile 32x16: warpM=(wid&1)*32, warpN=(wid>>1)*16.
// ===========================================================================
#define G5_OA  0
#define G5_OWH 10240
#define G5_OWL 15360
#define G5_BUF 20480
#define G5_SMEM (2 * G5_BUF)
#define G5_NIT (D_IN / 32)

__global__ __launch_bounds__(256, 4) void gemm1_v5(
    const float* __restrict__ A0, const float* __restrict__ A1,
    const float* __restrict__ A2,
    const __nv_bfloat16* __restrict__ Bh, const __nv_bfloat16* __restrict__ Bl,
    const float* __restrict__ bias,
    __nv_bfloat16* __restrict__ Oh, __nv_bfloat16* __restrict__ Ol) {
    extern __shared__ char sm[];
    const uint32_t sb = smem_u32(sm);
    const int tid = threadIdx.x;
    const int wid = tid >> 5, lane = tid & 31;
    const int warpM = (wid & 1) * 32;
    const int warpN = (wid >> 1) * 16;
    const int n0 = blockIdx.x * 64;
    const int m0 = blockIdx.y * 64;

    float acc[2][2][4];
    #pragma unroll
    for (int i = 0; i < 2; i++)
        #pragma unroll
        for (int j = 0; j < 2; j++)
            #pragma unroll
            for (int q = 0; q < 4; q++) acc[i][j][q] = 0.f;

    auto issue = [&](int it, int b) {
        const int k0 = it * 32;
        const float* Ap; int lda, kk;
        if (k0 < D_SUP)               { Ap = A0; lda = D_SUP;  kk = k0; }
        else if (k0 < D_SUP + D_ANOM) { Ap = A1; lda = D_ANOM; kk = k0 - D_SUP; }
        else                          { Ap = A2; lda = D_IND;  kk = k0 - D_SUP - D_ANOM; }
        const uint32_t bb = sb + b * G5_BUF;
        #pragma unroll
        for (int t = 0; t < 2; t++) {
            int idx = tid + t * 256;          // 512 float4 chunks of A (fp32, stride 144)
            int row = idx >> 3, q = idx & 7;
            cp16(bb + G5_OA + row * 144 + q * 16,
                 Ap + (size_t)(m0 + row) * lda + kk + q * 4);
        }
        #pragma unroll
        for (int t = 0; t < 2; t++) {
            int idx = tid + t * 256;          // 512 chunks of W (hi 256 + lo 256)
            int plane = idx >= 256;
            int cc = idx & 255;
            int row = cc >> 2, q = cc & 3;
            cp16(bb + (plane ? G5_OWL : G5_OWH) + row * 80 + q * 16,
                 (plane ? Bl : Bh) + (size_t)(n0 + row) * D_IN + k0 + q * 8);
        }
        CP_COMMIT();
    };

    issue(0, 0);

    for (int it = 0; it < G5_NIT; it++) {
        const int b = it & 1;
        const uint32_t bb = sb + b * G5_BUF;
        CP_WAIT0();
        __syncthreads();
        if (it + 1 < G5_NIT) issue(it + 1, b ^ 1);

        // in-place convert: stage fp32 to regs, sync, overwrite region hi/lo
        float4 v[2];
        #pragma unroll
        for (int t = 0; t < 2; t++) {
            int idx = tid + t * 256;
            int row = idx >> 3, q = idx & 7;
            v[t] = *(const float4*)(sm + (size_t)b * G5_BUF + G5_OA + row * 144 + q * 16);
        }
        __syncthreads();
        #pragma unroll
        for (int t = 0; t < 2; t++) {
            int idx = tid + t * 256;
            int row = idx >> 3, q = idx & 7;
            __nv_bfloat16 hx = __float2bfloat16(v[t].x), hy = __float2bfloat16(v[t].y);
            __nv_bfloat16 hz = __float2bfloat16(v[t].z), hw = __float2bfloat16(v[t].w);
            __nv_bfloat162 h01 = {hx, hy}, h23 = {hz, hw};
            __nv_bfloat162 l01 = __floats2bfloat162_rn(v[t].x - __bfloat162float(hx),
                                                       v[t].y - __bfloat162float(hy));
            __nv_bfloat162 l23 = __floats2bfloat162_rn(v[t].z - __bfloat162float(hz),
                                                       v[t].w - __bfloat162float(hw));
            size_t off = (size_t)b * G5_BUF + G5_OA + row * 80 + q * 8;
            *(__nv_bfloat162*)(sm + off) = h01;
            *(__nv_bfloat162*)(sm + off + 4) = h23;
            *(__nv_bfloat162*)(sm + off + 5120) = l01;
            *(__nv_bfloat162*)(sm + off + 5120 + 4) = l23;
        }
        __syncthreads();

        #pragma unroll
        for (int kq = 0; kq < 2; kq++) {
            const uint32_t colb = (uint32_t)(kq * 16 + ((lane >> 4) << 3)) * 2;
            uint32_t a_h[2][4], a_l[2][4], bh[2][2], bl[2][2];
            #pragma unroll
            for (int mt = 0; mt < 2; mt++) {
                uint32_t off = (uint32_t)(warpM + mt * 16 + (lane & 15)) * 80 + colb;
                ldsm4(a_h[mt], bb + G5_OA + off);
                ldsm4(a_l[mt], bb + G5_OA + 5120 + off);
            }
            {
                uint32_t off = (uint32_t)(warpN + (lane & 15)) * 80 + colb;
                uint32_t r[4];
                ldsm4(r, bb + G5_OWH + off);
                bh[0][0] = r[0]; bh[0][1] = r[2];
                bh[1][0] = r[1]; bh[1][1] = r[3];
                ldsm4(r, bb + G5_OWL + off);
                bl[0][0] = r[0]; bl[0][1] = r[2];
                bl[1][0] = r[1]; bl[1][1] = r[3];
            }
            #pragma unroll
            for (int mt = 0; mt < 2; mt++)
                #pragma unroll
                for (int nt = 0; nt < 2; nt++) mma_bf16(acc[mt][nt], a_h[mt], bh[nt]);
            #pragma unroll
            for (int mt = 0; mt < 2; mt++)
                #pragma unroll
                for (int nt = 0; nt < 2; nt++) mma_bf16(acc[mt][nt], a_l[mt], bh[nt]);
            #pragma unroll
            for (int mt = 0; mt < 2; mt++)
                #pragma unroll
                for (int nt = 0; nt < 2; nt++) mma_bf16(acc[mt][nt], a_h[mt], bl[nt]);
        }
    }

    // epilogue: bias + relu -> bf16 hi/lo
    #pragma unroll
    for (int mt = 0; mt < 2; mt++) {
        const int r0 = m0 + warpM + mt * 16 + (lane >> 2);
        #pragma unroll
        for (int nt = 0; nt < 2; nt++) {
            const int ng = n0 + warpN + nt * 8 + ((lane & 3) << 1);
            float2 bv = *(const float2*)(bias + ng);
            float v00 = fmaxf(acc[mt][nt][0] + bv.x, 0.f);
            float v01 = fmaxf(acc[mt][nt][1] + bv.y, 0.f);
            float v10 = fmaxf(acc[mt][nt][2] + bv.x, 0.f);
            float v11 = fmaxf(acc[mt][nt][3] + bv.y, 0.f);
            __nv_bfloat16 h00 = __float2bfloat16(v00), h01 = __float2bfloat16(v01);
            __nv_bfloat16 h10 = __float2bfloat16(v10), h11 = __float2bfloat16(v11);
            __nv_bfloat162 hi0 = {h00, h01}, hi1 = {h10, h11};
            __nv_bfloat162 lo0 = __floats2bfloat162_rn(v00 - __bfloat162float(h00),
                                                       v01 - __bfloat162float(h01));
            __nv_bfloat162 lo1 = __floats2bfloat162_rn(v10 - __bfloat162float(h10),
                                                       v11 - __bfloat162float(h11));
            *(__nv_bfloat162*)(Oh + (size_t)r0 * H1 + ng) = hi0;
            *(__nv_bfloat162*)(Ol + (size_t)r0 * H1 + ng) = lo0;
            *(__nv_bfloat162*)(Oh + (size_t)(r0 + 8) * H1 + ng) = hi1;
            *(__nv_bfloat162*)(Ol + (size_t)(r0 + 8) * H1 + ng) = lo1;
        }
    }
}

// ===========================================================================
// Fused tail (unchanged): GEMM2 + 12 layers + final retrieval.
// ===========================================================================
#define LDA 136
#define TAIL_SMEM ((128 * LDA * 2 + 256 * LDA * 2) * 2 + 256 * 4)

__global__ __launch_bounds__(512, 1) void fused_tail(
    const __nv_bfloat16* __restrict__ h1h, const __nv_bfloat16* __restrict__ h1l,
    const __nv_bfloat16* __restrict__ Wh2, const __nv_bfloat16* __restrict__ Wl2,
    const float* __restrict__ b2,
    const __nv_bfloat16* __restrict__ WhC, const __nv_bfloat16* __restrict__ WlC,
    const float* __restrict__ consB,
    const __nv_bfloat16* __restrict__ WfH, const __nv_bfloat16* __restrict__ WfL,
    const float* __restrict__ retB, const float* __restrict__ aw,
    float* __restrict__ out) {
    extern __shared__ __nv_bfloat16 smt[];
    __nv_bfloat16* sAh = smt;
    __nv_bfloat16* sAl = sAh + 128 * LDA;
    __nv_bfloat16* sWh = sAl + 128 * LDA;
    __nv_bfloat16* sWl = sWh + 256 * LDA;
    float* wsum = (float*)(sWl + 256 * LDA);
    float* saw  = wsum + 128;

    const int tid = threadIdx.x;
    const int wid = tid >> 5, lane = tid & 31;
    const int wm = wid & 3;
    const int wn = wid >> 2;
    const int m0 = blockIdx.x * 128;

    const uint32_t aAh = smem_u32(sAh), aAl = smem_u32(sAl);
    const uint32_t aWh = smem_u32(sWh), aWl = smem_u32(sWl);

    auto issueW = [&](const __nv_bfloat16* srcH, const __nv_bfloat16* srcL,
                      int srcStride, int slot) {
        #pragma unroll
        for (int t = 0; t < 8; t++) {
            int idx = tid + t * 512;
            int half = idx >= 2048;
            int cc = idx & 2047;
            int row = cc >> 4, q = cc & 15;
            const __nv_bfloat16* src = (half ? srcL : srcH) + (size_t)row * srcStride + q * 8;
            cp16((half ? aWl : aWh) + (uint32_t)((slot * 128 + row) * LDA + q * 8) * 2, src);
        }
        CP_COMMIT();
    };
    auto issueAct = [&](int kc) {
        #pragma unroll
        for (int t = 0; t < 8; t++) {
            int idx = tid + t * 512;
            int half = idx >= 2048;
            int cc = idx & 2047;
            int row = cc >> 4, q = cc & 15;
            const __nv_bfloat16* src = (half ? h1l : h1h)
                + (size_t)(m0 + row) * H1 + kc * 128 + q * 8;
            cp16((half ? aAl : aAh) + (uint32_t)(row * LDA + q * 8) * 2, src);
        }
        CP_COMMIT();
    };
    auto issueFin = [&](int k) {
        #pragma unroll
        for (int t = 0; t < 16; t++) {
            int idx = tid + t * 512;
            int half = idx >= 4096;
            int cc = idx & 4095;
            int row = cc >> 4, q = cc & 15;
            const __nv_bfloat16* src = (half ? WfL : WfH)
                + (size_t)k * 256 * FEAT + (size_t)row * FEAT + q * 8;
            cp16((half ? aWl : aWh) + (uint32_t)(row * LDA + q * 8) * 2, src);
        }
        CP_COMMIT();
    };

    auto mma128 = [&](float acc4[2][4][4], int slot) {
        const uint32_t base = (uint32_t)(slot * 128 * LDA) * 2;
        #pragma unroll
        for (int ch = 0; ch < 8; ch++) {
            const int colh = ch * 16 + ((lane >> 4) << 3);
            uint32_t a_h[2][4], a_l[2][4], bfr[4][2];
            #pragma unroll
            for (int mt = 0; mt < 2; mt++) {
                int row = wm * 32 + mt * 16 + (lane & 15);
                ldsm4(a_h[mt], aAh + (uint32_t)(row * LDA + colh) * 2);
                ldsm4(a_l[mt], aAl + (uint32_t)(row * LDA + colh) * 2);
            }
            #pragma unroll
            for (int nt2 = 0; nt2 < 2; nt2++) {
                int row = wn * 32 + nt2 * 16 + (lane & 15);
                uint32_t r[4];
                ldsm4(r, aWh + base + (uint32_t)(row * LDA + colh) * 2);
                bfr[2 * nt2][0] = r[0]; bfr[2 * nt2][1] = r[2];
                bfr[2 * nt2 + 1][0] = r[1]; bfr[2 * nt2 + 1][1] = r[3];
            }
            #pragma unroll
            for (int mt = 0; mt < 2; mt++)
                #pragma unroll
                for (int nt = 0; nt < 4; nt++) mma_bf16(acc4[mt][nt], a_h[mt], bfr[nt]);
            #pragma unroll
            for (int mt = 0; mt < 2; mt++)
                #pragma unroll
                for (int nt = 0; nt < 4; nt++) mma_bf16(acc4[mt][nt], a_l[mt], bfr[nt]);
            #pragma unroll
            for (int nt2 = 0; nt2 < 2; nt2++) {
                int row = wn * 32 + nt2 * 16 + (lane & 15);
                uint32_t r[4];
                ldsm4(r, aWl + base + (uint32_t)(row * LDA + colh) * 2);
                bfr[2 * nt2][0] = r[0]; bfr[2 * nt2][1] = r[2];
                bfr[2 * nt2 + 1][0] = r[1]; bfr[2 * nt2 + 1][1] = r[3];
            }
            #pragma unroll
            for (int mt = 0; mt < 2; mt++)
                #pragma unroll
                for (int nt = 0; nt < 4; nt++) mma_bf16(acc4[mt][nt], a_h[mt], bfr[nt]);
        }
    };
    auto epilogue = [&](float acc4[2][4][4], const float* biasp) {
        #pragma unroll
        for (int mt = 0; mt < 2; mt++) {
            const int row = wm * 32 + mt * 16 + (lane >> 2);
            #pragma unroll
            for (int nt = 0; nt < 4; nt++) {
                const int col = wn * 32 + nt * 8 + ((lane & 3) << 1);
                float2 bv = *(const float2*)(biasp + col);
                float v00 = fmaxf(acc4[mt][nt][0] + bv.x, 0.f);
                float v01 = fmaxf(acc4[mt][nt][1] + bv.y, 0.f);
                float v10 = fmaxf(acc4[mt][nt][2] + bv.x, 0.f);
                float v11 = fmaxf(acc4[mt][nt][3] + bv.y, 0.f);
                __nv_bfloat16 h00 = __float2bfloat16(v00), h01 = __float2bfloat16(v01);
                __nv_bfloat16 h10 = __float2bfloat16(v10), h11 = __float2bfloat16(v11);
                __nv_bfloat162 hi0 = {h00, h01}, hi1 = {h10, h11};
                __nv_bfloat162 lo0 = __floats2bfloat162_rn(v00 - __bfloat162float(h00),
                                                           v01 - __bfloat162float(h01));
                __nv_bfloat162 lo1 = __floats2bfloat162_rn(v10 - __bfloat162float(h10),
                                                           v11 - __bfloat162float(h11));
                *(__nv_bfloat162*)(sAh + row * LDA + col) = hi0;
                *(__nv_bfloat162*)(sAl + row * LDA + col) = lo0;
                *(__nv_bfloat162*)(sAh + (row + 8) * LDA + col) = hi1;
                *(__nv_bfloat162*)(sAl + (row + 8) * LDA + col) = lo1;
            }
        }
    };

    if (tid < 128) saw[tid] = aw[m0 + tid];

    issueW(Wh2, Wl2, H1, 0);
    issueAct(0);
    {
        #pragma unroll
        for (int t = 0; t < 8; t++) {
            int idx = tid + t * 512;
            int half = idx >= 2048;
            int cc = idx & 2047;
            int row = cc >> 4, q = cc & 15;
            const __nv_bfloat16* src = (half ? Wl2 : Wh2) + (size_t)row * H1 + 128 + q * 8;
            cp16((half ? aWl : aWh) + (uint32_t)((128 + row) * LDA + q * 8) * 2, src);
        }
        CP_COMMIT();
    }

    float acc4[2][4][4];
    #pragma unroll
    for (int i = 0; i < 2; i++)
        #pragma unroll
        for (int j = 0; j < 4; j++)
            #pragma unroll
            for (int q = 0; q < 4; q++) acc4[i][j][q] = 0.f;

    CP_WAIT1();
    __syncthreads();
    mma128(acc4, 0);
    __syncthreads();
    issueAct(1);
    issueW(WhC, WlC, FEAT, 0);
    CP_WAIT1();
    __syncthreads();
    mma128(acc4, 1);
    __syncthreads();
    epilogue(acc4, b2);
    __syncthreads();

    for (int l = 0; l < DEPTH; l++) {
        if (l + 1 < DEPTH)
            issueW(WhC + (size_t)(l + 1) * FEAT * FEAT,
                   WlC + (size_t)(l + 1) * FEAT * FEAT, FEAT, (l + 1) & 1);
        if (l + 1 < DEPTH) { CP_WAIT1(); } else { CP_WAIT0(); }
        __syncthreads();
        #pragma unroll
        for (int i = 0; i < 2; i++)
            #pragma unroll
            for (int j = 0; j < 4; j++)
                #pragma unroll
                for (int q = 0; q < 4; q++) acc4[i][j][q] = 0.f;
        mma128(acc4, l & 1);
        __syncthreads();
        epilogue(acc4, consB + (size_t)l * FEAT);
        __syncthreads();
    }

    issueFin(0);
    CP_WAIT0();
    const float cfac = 0.42f * 1.8f / (float)CAP;
    for (int k = 0; k < NCOND; k++) {
        __syncthreads();
        if (tid < 128) wsum[tid] = 0.f;

        float acc8[2][8][4];
        #pragma unroll
        for (int i = 0; i < 2; i++)
            #pragma unroll
            for (int j = 0; j < 8; j++)
                #pragma unroll
                for (int q = 0; q < 4; q++) acc8[i][j][q] = 0.f;

        #pragma unroll
        for (int ch = 0; ch < 8; ch++) {
            const int colh = ch * 16 + ((lane >> 4) << 3);
            uint32_t a_h[2][4], a_l[2][4], bfr[8][2];
            #pragma unroll
            for (int mt = 0; mt < 2; mt++) {
                int row = wm * 32 + mt * 16 + (lane & 15);
                ldsm4(a_h[mt], aAh + (uint32_t)(row * LDA + colh) * 2);
                ldsm4(a_l[mt], aAl + (uint32_t)(row * LDA + colh) * 2);
            }
            #pragma unroll
            for (int nt2 = 0; nt2 < 4; nt2++) {
                int row = wn * 64 + nt2 * 16 + (lane & 15);
                uint32_t r[4];
                ldsm4(r, aWh + (uint32_t)(row * LDA + colh) * 2);
                bfr[2 * nt2][0] = r[0]; bfr[2 * nt2][1] = r[2];
                bfr[2 * nt2 + 1][0] = r[1]; bfr[2 * nt2 + 1][1] = r[3];
            }
            #pragma unroll
            for (int mt = 0; mt < 2; mt++)
                #pragma unroll
                for (int nt = 0; nt < 8; nt++) mma_bf16(acc8[mt][nt], a_h[mt], bfr[nt]);
            #pragma unroll
            for (int mt = 0; mt < 2; mt++)
                #pragma unroll
                for (int nt = 0; nt < 8; nt++) mma_bf16(acc8[mt][nt], a_l[mt], bfr[nt]);
            #pragma unroll
            for (int nt2 = 0; nt2 < 4; nt2++) {
                int row = wn * 64 + nt2 * 16 + (lane & 15);
                uint32_t r[4];
                ldsm4(r, aWl + (uint32_t)(row * LDA + colh) * 2);
                bfr[2 * nt2][0] = r[0]; bfr[2 * nt2][1] = r[2];
                bfr[2 * nt2 + 1][0] = r[1]; bfr[2 * nt2 + 1][1] = r[3];
            }
            #pragma unroll
            for (int mt = 0; mt < 2; mt++)
                #pragma unroll
                for (int nt = 0; nt < 8; nt++) mma_bf16(acc8[mt][nt], a_h[mt], bfr[nt]);
        }
        __syncthreads();
        if (k + 1 < NCOND) issueFin(k + 1);

        if (wn >= 2) {
            #pragma unroll
            for (int mt = 0; mt < 2; mt++) {
                const int r1 = wm * 32 + mt * 16 + (lane >> 2);
                float p1 = 0.f, p2 = 0.f;
                #pragma unroll
                for (int nt = 0; nt < 8; nt++) {
                    const int e0 = (wn - 2) * 64 + nt * 8 + ((lane & 3) << 1);
                    float m00 = __bfloat162float(sAh[r1 * LDA + e0]) +
                                __bfloat162float(sAl[r1 * LDA + e0]);
                    float m01 = __bfloat162float(sAh[r1 * LDA + e0 + 1]) +
                                __bfloat162float(sAl[r1 * LDA + e0 + 1]);
                    float m10 = __bfloat162float(sAh[(r1 + 8) * LDA + e0]) +
                                __bfloat162float(sAl[(r1 + 8) * LDA + e0]);
                    float m11 = __bfloat162float(sAh[(r1 + 8) * LDA + e0 + 1]) +
                                __bfloat162float(sAl[(r1 + 8) * LDA + e0 + 1]);
                    p1 += acc8[mt][nt][0] * m00 + acc8[mt][nt][1] * m01;
                    p2 += acc8[mt][nt][2] * m10 + acc8[mt][nt][3] * m11;
                }
                atomicAdd(&wsum[r1], p1);
                atomicAdd(&wsum[r1 + 8], p2);
            }
        }
        __syncthreads();
        if (tid < 128) wsum[tid] = wsum[tid] * cfac + 0.3f * saw[tid];
        __syncthreads();

        if (wn < 2) {
            #pragma unroll
            for (int mt = 0; mt < 2; mt++) {
                const int rl = wm * 32 + mt * 16 + (lane >> 2);
                const float w1 = wsum[rl], w2 = wsum[rl + 8];
                #pragma unroll
                for (int nt = 0; nt < 8; nt++) {
                    const int col = wn * 64 + nt * 8 + ((lane & 3) << 1);
                    float2 bv = *(const float2*)(retB + (size_t)k * FEAT + col);
                    size_t base1 = (size_t)(m0 + rl) * (NCOND * FEAT) + (size_t)k * FEAT + col;
                    size_t base2 = (size_t)(m0 + rl + 8) * (NCOND * FEAT) + (size_t)k * FEAT + col;
                    *(float2*)(out + base1) = make_float2((acc8[mt][nt][0] + bv.x) * w1,
                                                          (acc8[mt][nt][1] + bv.y) * w1);
                    *(float2*)(out + base2) = make_float2((acc8[mt][nt][2] + bv.x) * w2,
                                                          (acc8[mt][nt][3] + bv.y) * w2);
                }
            }
        }
        if (k + 1 < NCOND) CP_WAIT0();
    }
}

// ===========================================================================
extern "C" void kernel_launch(void* const* d_in, const int* in_sizes, int n_in,
                              void* d_out, int out_size) {
    const float* sup  = (const float*)d_in[0];
    const float* anom = (const float*)d_in[1];
    const float* ind  = (const float*)d_in[2];
    const float* ipW1 = (const float*)d_in[3];
    const float* ipb1 = (const float*)d_in[4];
    const float* ipW2 = (const float*)d_in[5];
    const float* ipb2 = (const float*)d_in[6];
    const float* consW = (const float*)d_in[7];
    const float* consB = (const float*)d_in[8];
    const float* refp = (const float*)d_in[9];
    const float* objp = (const float*)d_in[10];
    const float* retW = (const float*)d_in[11];
    const float* retB = (const float*)d_in[12];
    float* out = (float*)d_out;

    __nv_bfloat16 *Wh1, *Wl1, *Wh2, *Wl2, *WhC, *WlC, *h1h, *h1l, *WfH, *WfL;
    float *aw;
    cudaGetSymbolAddress((void**)&Wh1, g_Wh1);
    cudaGetSymbolAddress((void**)&Wl1, g_Wl1);
    cudaGetSymbolAddress((void**)&Wh2, g_Wh2);
    cudaGetSymbolAddress((void**)&Wl2, g_Wl2);
    cudaGetSymbolAddress((void**)&WhC, g_WhC);
    cudaGetSymbolAddress((void**)&WlC, g_WlC);
    cudaGetSymbolAddress((void**)&h1h, g_h1h);
    cudaGetSymbolAddress((void**)&h1l, g_h1l);
    cudaGetSymbolAddress((void**)&WfH, g_WfinH);
    cudaGetSymbolAddress((void**)&WfL, g_WfinL);
    cudaGetSymbolAddress((void**)&aw, g_aw);

    cudaFuncSetAttribute(gemm1_v5, cudaFuncAttributeMaxDynamicSharedMemorySize, G5_SMEM);
    cudaFuncSetAttribute(fused_tail, cudaFuncAttributeMaxDynamicSharedMemorySize, TAIL_SMEM);

    // ncu captures kernel_launch's 4th launch (harness issues 2 before ours).
    tsplit_kernel<<<dim3(D_IN / 32, H1 / 32, 1), dim3(32, 8)>>>(ipW1, Wh1, Wl1, D_IN, H1, H1 * D_IN); // 1
    aw_kernel<<<BB * 32 / 256, 256>>>(anom, aw);                                      // 2
    mkfin_kernel<<<NCOND, 256>>>(refp, objp, WfH, WfL);                               // 3
    gemm1_v5<<<dim3(4, BB / 64), 256, G5_SMEM>>>(sup, anom, ind, Wh1, Wl1, ipb1, h1h, h1l); // 4 (profiled)
    tsplit_kernel<<<dim3(H1 / 32, FEAT / 32, 1), dim3(32, 8)>>>(ipW2, Wh2, Wl2, H1, FEAT, FEAT * H1); // 5
    tsplit_kernel<<<dim3(FEAT / 32, FEAT / 32, DEPTH), dim3(32, 8)>>>(consW, WhC, WlC, FEAT, FEAT, FEAT * FEAT); // 6
    tsplit_kernel<<<dim3(FEAT / 32, FEAT / 32, NCOND), dim3(32, 8)>>>(retW, WfH, WfL, FEAT, FEAT, 256 * FEAT);   // 7
    fused_tail<<<BB / 128, 512, TAIL_SMEM>>>(
        h1h, h1l, Wh2, Wl2, ipb2, WhC, WlC, consB, WfH, WfL, retB, aw, out);          // 8
}